// round 8
// baseline (speedup 1.0000x reference)
#include <cuda_runtime.h>
#include <cstdint>
#include <cstddef>

#define N      16384
#define C      128
#define KNN    9
#define KCAND  16
#define COUT   256
#define STRIP  1024            // 64 MB strip -> L2-resident
#define NSTRIP (N / STRIP)
#define BUFCAP 1024

// Scratch (static __device__ arrays per harness rules; no cudaMalloc anywhere)
__device__ float g_sq[N];
__device__ float g_dist[(size_t)STRIP * N];   // 64 MB strip, L2-resident
__device__ int   g_cand[N * KCAND];
__device__ int   g_nbr[N * KNN];
__device__ float g_x2[(size_t)N * C];

// ---------------------------------------------------------------------------
// 1) squared norms -- replicate an LLVM/XLA vectorized reduce:
//    VF=4, IC=2 -> 8 stride-8 fmaf partial sums, lane-wise combine of the two
//    interleaved vectors, then horizontal tree (l0+l2)+(l1+l3).
// ---------------------------------------------------------------------------
__global__ void sqnorm_kernel(const float* __restrict__ x) {
    int i = blockIdx.x * blockDim.x + threadIdx.x;
    if (i >= N) return;
    const float* r = x + (size_t)i * C;
    float p[8];
#pragma unroll
    for (int l = 0; l < 8; l++) p[l] = 0.f;
#pragma unroll
    for (int k = 0; k < C / 8; k++)
#pragma unroll
        for (int l = 0; l < 8; l++) {
            float v = r[8 * k + l];
            p[l] = fmaf(v, v, p[l]);
        }
    float v0 = p[0] + p[4];
    float v1 = p[1] + p[5];
    float v2 = p[2] + p[6];
    float v3 = p[3] + p[7];
    g_sq[i] = (v0 + v2) + (v1 + v3);
}

// ---------------------------------------------------------------------------
// 2) distance GEMM strip (candidate nomination) using packed fma.rn.f32x2.
//    Each accumulator u64 packs two ADJACENT output columns; lane-wise fp32 RN
//    keeps every column's ascending-k FMA chain bitwise identical to FFMA.
//    dist[i - row0][j] = (sq[i] + sq[j]) - 2 * x_i . x_j
// ---------------------------------------------------------------------------
__global__ __launch_bounds__(256, 2)
void dist_kernel(const float* __restrict__ x, int row0) {
    __shared__ float As[32][132];   // [k][m] transposed
    __shared__ float Bs[32][132];   // [k][n] transposed

    const int bi  = row0 + blockIdx.y * 128;
    const int bj  = blockIdx.x * 128;
    const int tid = threadIdx.x;
    const int tm  = (tid >> 4) << 3;   // 0..120
    const int tn  = (tid & 15) << 3;   // 0..120

    unsigned long long acc2[8][4];     // [a][b-pair]: cols (2q, 2q+1)
#pragma unroll
    for (int a = 0; a < 8; a++)
#pragma unroll
        for (int q = 0; q < 4; q++) acc2[a][q] = 0ULL;

    for (int k0 = 0; k0 < C; k0 += 32) {
#pragma unroll
        for (int v = 0; v < 4; v++) {
            int idx = tid + v * 256;       // 0..1023
            int r   = idx >> 3;            // 0..127
            int c4  = (idx & 7) << 2;      // 0,4,...,28
            float4 a = *reinterpret_cast<const float4*>(&x[(size_t)(bi + r) * C + k0 + c4]);
            As[c4 + 0][r] = a.x; As[c4 + 1][r] = a.y;
            As[c4 + 2][r] = a.z; As[c4 + 3][r] = a.w;
            float4 bb = *reinterpret_cast<const float4*>(&x[(size_t)(bj + r) * C + k0 + c4]);
            Bs[c4 + 0][r] = bb.x; Bs[c4 + 1][r] = bb.y;
            Bs[c4 + 2][r] = bb.z; Bs[c4 + 3][r] = bb.w;
        }
        __syncthreads();
#pragma unroll
        for (int k = 0; k < 32; k++) {
            float av[8];
            float bv[8];
            *reinterpret_cast<float4*>(&av[0]) = *reinterpret_cast<const float4*>(&As[k][tm]);
            *reinterpret_cast<float4*>(&av[4]) = *reinterpret_cast<const float4*>(&As[k][tm + 4]);
            *reinterpret_cast<float4*>(&bv[0]) = *reinterpret_cast<const float4*>(&Bs[k][tn]);
            *reinterpret_cast<float4*>(&bv[4]) = *reinterpret_cast<const float4*>(&Bs[k][tn + 4]);
            unsigned long long bv2[4];
#pragma unroll
            for (int q = 0; q < 4; q++)
                asm("mov.b64 %0, {%1, %2};" : "=l"(bv2[q])
                    : "r"(__float_as_uint(bv[2 * q])), "r"(__float_as_uint(bv[2 * q + 1])));
#pragma unroll
            for (int a = 0; a < 8; a++) {
                unsigned long long av2;
                asm("mov.b64 %0, {%1, %1};" : "=l"(av2) : "r"(__float_as_uint(av[a])));
#pragma unroll
                for (int q = 0; q < 4; q++)
                    asm("fma.rn.f32x2 %0, %1, %2, %3;"
                        : "=l"(acc2[a][q]) : "l"(av2), "l"(bv2[q]), "l"(acc2[a][q]));
            }
        }
        __syncthreads();
    }

    const float INFV = __int_as_float(0x7f800000);
#pragma unroll
    for (int a = 0; a < 8; a++) {
        int i      = bi + tm + a;
        int lrow   = i - row0;
        float sqi  = g_sq[i];
        float rowv[8];
#pragma unroll
        for (int q = 0; q < 4; q++) {
            unsigned lo, hi;
            asm("mov.b64 {%0, %1}, %2;" : "=r"(lo), "=r"(hi) : "l"(acc2[a][q]));
            int j0 = bj + tn + 2 * q;
            float d0 = (sqi + g_sq[j0])     - 2.f * __uint_as_float(lo);
            float d1 = (sqi + g_sq[j0 + 1]) - 2.f * __uint_as_float(hi);
            if (i == j0)     d0 = INFV;
            if (i == j0 + 1) d1 = INFV;
            rowv[2 * q]     = d0;
            rowv[2 * q + 1] = d1;
        }
        float* dst = &g_dist[(size_t)lrow * N + bj + tn];
        *reinterpret_cast<float4*>(dst)     = *reinterpret_cast<float4*>(&rowv[0]);
        *reinterpret_cast<float4*>(dst + 4) = *reinterpret_cast<float4*>(&rowv[4]);
    }
}

// ---------------------------------------------------------------------------
// 3) per-row top-16 via deterministic threshold two-sweep.
//    Sweep 1: per-thread min of 64 elems -> tau = 16th smallest of the 256
//    thread-minima (each is a distinct element => >=16 elements <= tau).
//    Sweep 2: compact all elements <= tau, then rank-select by (val, idx).
//    Result: exact top-16 by (value, index) -- identical to prior rounds.
// ---------------------------------------------------------------------------
__global__ __launch_bounds__(256)
void topk_kernel(int row0) {
    __shared__ float smin[256];
    __shared__ int   sidx[256];
    __shared__ float s_tau;
    __shared__ int   s_cnt;
    __shared__ float bval[BUFCAP];
    __shared__ int   bidx[BUFCAP];

    const int lrow = blockIdx.x;
    const int row  = row0 + lrow;
    const float* d = g_dist + (size_t)lrow * N;
    const int tid  = threadIdx.x;
    const float INFV = __int_as_float(0x7f800000);

    // sweep 1: per-thread min (strict <, ascending index => lowest-index win)
    const float4* d4 = reinterpret_cast<const float4*>(d);
    float mv = INFV;
    int   mi = 0x7fffffff;
#pragma unroll 4
    for (int it = 0; it < N / (256 * 4); it++) {
        float4 q = d4[it * 256 + tid];
        int jb = (it * 256 + tid) * 4;
        if (q.x < mv) { mv = q.x; mi = jb; }
        if (q.y < mv) { mv = q.y; mi = jb + 1; }
        if (q.z < mv) { mv = q.z; mi = jb + 2; }
        if (q.w < mv) { mv = q.w; mi = jb + 3; }
    }
    smin[tid] = mv; sidx[tid] = mi;
    if (tid == 0) s_cnt = 0;
    __syncthreads();

    // tau = value of the rank-15 minimum (total order by (val, idx))
    int rank = 0;
#pragma unroll 8
    for (int t = 0; t < 256; t++) {
        float ov = smin[t];
        rank += (ov < mv) || (ov == mv && sidx[t] < mi);
    }
    if (rank == 15) s_tau = mv;
    __syncthreads();
    const float tau = s_tau;

    // sweep 2: compact all elements <= tau (expected ~20-30)
#pragma unroll 4
    for (int it = 0; it < N / (256 * 4); it++) {
        float4 q = d4[it * 256 + tid];
        int jb = (it * 256 + tid) * 4;
        float vv[4] = {q.x, q.y, q.z, q.w};
#pragma unroll
        for (int e = 0; e < 4; e++) {
            if (vv[e] <= tau) {
                int p = atomicAdd(&s_cnt, 1);
                if (p < BUFCAP) { bval[p] = vv[e]; bidx[p] = jb + e; }
            }
        }
    }
    __syncthreads();
    const int m = (s_cnt < BUFCAP) ? s_cnt : BUFCAP;

    // rank-select: entry e's rank = #{f : (v_f, i_f) < (v_e, i_e)}
    for (int e = tid; e < m; e += 256) {
        float v = bval[e];
        int   j = bidx[e];
        int r = 0;
        for (int t = 0; t < m; t++) {
            float ov = bval[t];
            r += (ov < v) || (ov == v && bidx[t] < j);
        }
        if (r < KCAND) g_cand[row * KCAND + r] = j;
    }
}

// ---------------------------------------------------------------------------
// 3b) authoritative fp32 re-rank of the 16 candidates, replicating the
//     reference arithmetic: dot = single ascending-k fp32 FMA chain,
//     d = (sq_i + sq_j) - 2*dot, tie-break by lower index.
//     One warp per row; lane t owns candidate t.
// ---------------------------------------------------------------------------
__global__ __launch_bounds__(128)
void refine_kernel(const float* __restrict__ x) {
    __shared__ float sxi[4][128];
    const int warp = threadIdx.x >> 5;
    const int lane = threadIdx.x & 31;
    const int row  = blockIdx.x * 4 + warp;

#pragma unroll
    for (int q = 0; q < 4; q++)
        sxi[warp][lane + 32 * q] = x[(size_t)row * C + lane + 32 * q];
    __syncwarp();

    float d = __int_as_float(0x7f800000);
    int   j = 0x7fffffff;
    if (lane < KCAND) {
        j = g_cand[row * KCAND + lane];
        const float* xj = x + (size_t)j * C;
        float acc = 0.f;
#pragma unroll
        for (int k = 0; k < C; k += 4) {
            float4 v = *reinterpret_cast<const float4*>(xj + k);
            acc = fmaf(sxi[warp][k + 0], v.x, acc);
            acc = fmaf(sxi[warp][k + 1], v.y, acc);
            acc = fmaf(sxi[warp][k + 2], v.z, acc);
            acc = fmaf(sxi[warp][k + 3], v.w, acc);
        }
        d = (g_sq[row] + g_sq[j]) - 2.f * acc;
    }

    // lane 0 gathers, sorts by (d, index) with a static bubble network
    float dv[KCAND];
    int   di[KCAND];
#pragma unroll
    for (int t = 0; t < KCAND; t++) {
        dv[t] = __shfl_sync(0xffffffffu, d, t);
        di[t] = __shfl_sync(0xffffffffu, j, t);
    }
    if (lane == 0) {
#pragma unroll
        for (int a = 0; a < KCAND - 1; a++)
#pragma unroll
            for (int bq = 0; bq < KCAND - 1; bq++) {
                bool sw = dv[bq] > dv[bq + 1] ||
                          (dv[bq] == dv[bq + 1] && di[bq] > di[bq + 1]);
                float tv = sw ? dv[bq + 1] : dv[bq];
                dv[bq + 1] = sw ? dv[bq] : dv[bq + 1]; dv[bq] = tv;
                int ti = sw ? di[bq + 1] : di[bq];
                di[bq + 1] = sw ? di[bq] : di[bq + 1]; di[bq] = ti;
            }
#pragma unroll
        for (int t = 0; t < KNN; t++) g_nbr[row * KNN + t] = di[t];
    }
}

// ---------------------------------------------------------------------------
// 4) x2 = x + rel_pos_table[rel], rel[i] = i/128 - i%128 + 127
// ---------------------------------------------------------------------------
__global__ void relpos_kernel(const float* __restrict__ x, const float* __restrict__ tab) {
    int idx = blockIdx.x * blockDim.x + threadIdx.x;   // over N*C
    int i   = idx >> 7;
    int c   = idx & 127;
    int rel = (i >> 7) - (i & 127) + (C - 1);
    g_x2[idx] = x[idx] + tab[(size_t)rel * C + c];
}

// ---------------------------------------------------------------------------
// 5) gather + max-relative + concat-GEMM (+ bias at the end). 16 rows/block.
// ---------------------------------------------------------------------------
__global__ __launch_bounds__(256)
void final_kernel(const float* __restrict__ W, const float* __restrict__ b,
                  float* __restrict__ out) {
    __shared__ float feat[16][260];   // [x2 | m], padded row
    const int r0   = blockIdx.x * 16;
    const int tid  = threadIdx.x;
    const int half = tid >> 7;
    const int c    = tid & 127;
    const float NEGINF = __int_as_float(0xff800000);

#pragma unroll
    for (int rr = 0; rr < 16; rr += 2) {
        int r = rr + half;
        int i = r0 + r;
        float xi = g_x2[(size_t)i * C + c];
        float m  = NEGINF;
#pragma unroll
        for (int k = 0; k < KNN; k++) {
            int j = g_nbr[i * KNN + k];
            m = fmaxf(m, g_x2[(size_t)j * C + c] - xi);
        }
        feat[r][c]     = xi;
        feat[r][C + c] = m;
    }
    __syncthreads();

    const int o = tid;   // output column 0..255
    float acc[16];
#pragma unroll
    for (int r = 0; r < 16; r++) acc[r] = 0.f;

    for (int f = 0; f < 2 * C; f += 4) {
        float w0 = W[(size_t)(f + 0) * COUT + o];
        float w1 = W[(size_t)(f + 1) * COUT + o];
        float w2 = W[(size_t)(f + 2) * COUT + o];
        float w3 = W[(size_t)(f + 3) * COUT + o];
#pragma unroll
        for (int r = 0; r < 16; r++) {
            float4 fv = *reinterpret_cast<const float4*>(&feat[r][f]);
            acc[r] = fmaf(fv.x, w0, acc[r]);
            acc[r] = fmaf(fv.y, w1, acc[r]);
            acc[r] = fmaf(fv.z, w2, acc[r]);
            acc[r] = fmaf(fv.w, w3, acc[r]);
        }
    }
    float bias = b[o];
#pragma unroll
    for (int r = 0; r < 16; r++)
        out[(size_t)(r0 + r) * COUT + o] = acc[r] + bias;
}

// ---------------------------------------------------------------------------
extern "C" void kernel_launch(void* const* d_in, const int* in_sizes, int n_in,
                              void* d_out, int out_size) {
    const float* x   = (const float*)d_in[0];
    const float* tab = (const float*)d_in[1];
    const float* W   = (const float*)d_in[2];
    const float* b   = (const float*)d_in[3];
    float* out = (float*)d_out;
    (void)in_sizes; (void)n_in; (void)out_size;

    sqnorm_kernel<<<(N + 255) / 256, 256>>>(x);
    for (int s = 0; s < NSTRIP; s++) {
        dist_kernel<<<dim3(N / 128, STRIP / 128), 256>>>(x, s * STRIP);
        topk_kernel<<<STRIP, 256>>>(s * STRIP);
    }
    refine_kernel<<<N / 4, 128>>>(x);
    relpos_kernel<<<(N * C) / 256, 256>>>(x, tab);
    final_kernel<<<N / 16, 256>>>(W, b, out);
}

// round 9
// speedup vs baseline: 1.6264x; 1.6264x over previous
#include <cuda_runtime.h>
#include <cstdint>
#include <cstddef>

#define N      16384
#define C      128
#define KNN    9
#define KCAND  16
#define COUT   256
#define STRIP  1024            // 64 MB strip -> L2-resident
#define NSTRIP (N / STRIP)
#define BUFCAP 1024
#define SPITCH 36              // smem row pitch in words (16B-aligned rows, conflict-free frags)

// Scratch (static __device__ arrays per harness rules; no cudaMalloc anywhere)
__device__ float g_sq[N];
__device__ float g_dist[(size_t)STRIP * N];   // 64 MB strip, L2-resident
__device__ int   g_cand[N * KCAND];
__device__ int   g_nbr[N * KNN];
__device__ float g_x2[(size_t)N * C];

__device__ __forceinline__ uint32_t f2tf32(float f) {
    uint32_t u;
    asm("cvt.rna.tf32.f32 %0, %1;" : "=r"(u) : "f"(f));
    return u;
}

// ---------------------------------------------------------------------------
// 1) squared norms -- replicate an LLVM/XLA vectorized reduce:
//    VF=4, IC=2 -> 8 stride-8 fmaf partial sums, lane-wise combine of the two
//    interleaved vectors, then horizontal tree (l0+l2)+(l1+l3).
// ---------------------------------------------------------------------------
__global__ void sqnorm_kernel(const float* __restrict__ x) {
    int i = blockIdx.x * blockDim.x + threadIdx.x;
    if (i >= N) return;
    const float* r = x + (size_t)i * C;
    float p[8];
#pragma unroll
    for (int l = 0; l < 8; l++) p[l] = 0.f;
#pragma unroll
    for (int k = 0; k < C / 8; k++)
#pragma unroll
        for (int l = 0; l < 8; l++) {
            float v = r[8 * k + l];
            p[l] = fmaf(v, v, p[l]);
        }
    float v0 = p[0] + p[4];
    float v1 = p[1] + p[5];
    float v2 = p[2] + p[6];
    float v3 = p[3] + p[7];
    g_sq[i] = (v0 + v2) + (v1 + v3);
}

// ---------------------------------------------------------------------------
// 2) distance GEMM strip via tf32 tensor-core mma.sync (nomination only --
//    the fp32-exact refine pass below is the ranking authority).
//    dist[i - row0][j] = (sq[i] + sq[j]) - 2 * <x_i, x_j>_tf32
// ---------------------------------------------------------------------------
__global__ __launch_bounds__(256, 2)
void dist_kernel(const float* __restrict__ x, int row0) {
    __shared__ uint32_t As[128 * SPITCH];   // [m][k] tf32
    __shared__ uint32_t Bs[128 * SPITCH];   // [n][k] tf32

    const int tid  = threadIdx.x;
    const int warp = tid >> 5;
    const int lane = tid & 31;
    const int g    = lane >> 2;     // groupID
    const int tig  = lane & 3;      // thread-in-group
    const int wm   = warp & 3;      // warp row  (32 rows)
    const int wn   = warp >> 2;     // warp col  (64 cols)
    const int bi   = row0 + blockIdx.y * 128;
    const int bj   = blockIdx.x * 128;

    float acc[2][8][4];
#pragma unroll
    for (int mt = 0; mt < 2; mt++)
#pragma unroll
        for (int nt = 0; nt < 8; nt++)
#pragma unroll
            for (int e = 0; e < 4; e++) acc[mt][nt][e] = 0.f;

    for (int kc = 0; kc < 4; kc++) {
        // stage 128x32 A and B chunks, rounding to tf32
#pragma unroll
        for (int v = 0; v < 4; v++) {
            int idx = tid + v * 256;         // 0..1023
            int row = idx >> 3;              // 0..127
            int c4  = (idx & 7) << 2;        // 0..28
            float4 a = *reinterpret_cast<const float4*>(&x[(size_t)(bi + row) * C + kc * 32 + c4]);
            uint4 ua = make_uint4(f2tf32(a.x), f2tf32(a.y), f2tf32(a.z), f2tf32(a.w));
            *reinterpret_cast<uint4*>(&As[row * SPITCH + c4]) = ua;
            float4 bb = *reinterpret_cast<const float4*>(&x[(size_t)(bj + row) * C + kc * 32 + c4]);
            uint4 ub = make_uint4(f2tf32(bb.x), f2tf32(bb.y), f2tf32(bb.z), f2tf32(bb.w));
            *reinterpret_cast<uint4*>(&Bs[row * SPITCH + c4]) = ub;
        }
        __syncthreads();

#pragma unroll
        for (int ks = 0; ks < 4; ks++) {
            const int k0 = ks * 8;
            uint32_t a[2][4];
#pragma unroll
            for (int mt = 0; mt < 2; mt++) {
                int rbase = (wm * 32 + mt * 16 + g) * SPITCH + k0 + tig;
                a[mt][0] = As[rbase];
                a[mt][1] = As[rbase + 8 * SPITCH];
                a[mt][2] = As[rbase + 4];
                a[mt][3] = As[rbase + 8 * SPITCH + 4];
            }
            uint32_t b[8][2];
#pragma unroll
            for (int nt = 0; nt < 8; nt++) {
                int cbase = (wn * 64 + nt * 8 + g) * SPITCH + k0 + tig;
                b[nt][0] = Bs[cbase];
                b[nt][1] = Bs[cbase + 4];
            }
#pragma unroll
            for (int mt = 0; mt < 2; mt++)
#pragma unroll
                for (int nt = 0; nt < 8; nt++)
                    asm volatile(
                        "mma.sync.aligned.m16n8k8.row.col.f32.tf32.tf32.f32 "
                        "{%0,%1,%2,%3}, {%4,%5,%6,%7}, {%8,%9}, {%0,%1,%2,%3};"
                        : "+f"(acc[mt][nt][0]), "+f"(acc[mt][nt][1]),
                          "+f"(acc[mt][nt][2]), "+f"(acc[mt][nt][3])
                        : "r"(a[mt][0]), "r"(a[mt][1]), "r"(a[mt][2]), "r"(a[mt][3]),
                          "r"(b[nt][0]), "r"(b[nt][1]));
        }
        __syncthreads();
    }

    const float INFV = __int_as_float(0x7f800000);
#pragma unroll
    for (int mt = 0; mt < 2; mt++) {
        int r_lo = bi + wm * 32 + mt * 16 + g;
        int r_hi = r_lo + 8;
        float si_lo = g_sq[r_lo], si_hi = g_sq[r_hi];
#pragma unroll
        for (int nt = 0; nt < 8; nt++) {
            int c0 = bj + wn * 64 + nt * 8 + 2 * tig;
            float sj0 = g_sq[c0], sj1 = g_sq[c0 + 1];
            float d00 = (si_lo + sj0) - 2.f * acc[mt][nt][0];
            float d01 = (si_lo + sj1) - 2.f * acc[mt][nt][1];
            float d10 = (si_hi + sj0) - 2.f * acc[mt][nt][2];
            float d11 = (si_hi + sj1) - 2.f * acc[mt][nt][3];
            if (r_lo == c0)     d00 = INFV;
            if (r_lo == c0 + 1) d01 = INFV;
            if (r_hi == c0)     d10 = INFV;
            if (r_hi == c0 + 1) d11 = INFV;
            *reinterpret_cast<float2*>(&g_dist[(size_t)(r_lo - row0) * N + c0]) =
                make_float2(d00, d01);
            *reinterpret_cast<float2*>(&g_dist[(size_t)(r_hi - row0) * N + c0]) =
                make_float2(d10, d11);
        }
    }
}

// ---------------------------------------------------------------------------
// 3) per-row top-16 via deterministic threshold two-sweep.
//    Sweep 1: per-thread min of 64 elems -> tau = 16th smallest of the 256
//    thread-minima (each is a distinct element => >=16 elements <= tau).
//    Sweep 2: compact all elements <= tau, then rank-select by (val, idx).
// ---------------------------------------------------------------------------
__global__ __launch_bounds__(256)
void topk_kernel(int row0) {
    __shared__ float smin[256];
    __shared__ int   sidx[256];
    __shared__ float s_tau;
    __shared__ int   s_cnt;
    __shared__ float bval[BUFCAP];
    __shared__ int   bidx[BUFCAP];

    const int lrow = blockIdx.x;
    const int row  = row0 + lrow;
    const float* d = g_dist + (size_t)lrow * N;
    const int tid  = threadIdx.x;
    const float INFV = __int_as_float(0x7f800000);

    // sweep 1: per-thread min (strict <, ascending index => lowest-index win)
    const float4* d4 = reinterpret_cast<const float4*>(d);
    float mv = INFV;
    int   mi = 0x7fffffff;
#pragma unroll 4
    for (int it = 0; it < N / (256 * 4); it++) {
        float4 q = d4[it * 256 + tid];
        int jb = (it * 256 + tid) * 4;
        if (q.x < mv) { mv = q.x; mi = jb; }
        if (q.y < mv) { mv = q.y; mi = jb + 1; }
        if (q.z < mv) { mv = q.z; mi = jb + 2; }
        if (q.w < mv) { mv = q.w; mi = jb + 3; }
    }
    smin[tid] = mv; sidx[tid] = mi;
    if (tid == 0) s_cnt = 0;
    __syncthreads();

    // tau = value of the rank-15 minimum (total order by (val, idx))
    int rank = 0;
#pragma unroll 8
    for (int t = 0; t < 256; t++) {
        float ov = smin[t];
        rank += (ov < mv) || (ov == mv && sidx[t] < mi);
    }
    if (rank == 15) s_tau = mv;
    __syncthreads();
    const float tau = s_tau;

    // sweep 2: compact all elements <= tau (expected ~20-30)
#pragma unroll 4
    for (int it = 0; it < N / (256 * 4); it++) {
        float4 q = d4[it * 256 + tid];
        int jb = (it * 256 + tid) * 4;
        float vv[4] = {q.x, q.y, q.z, q.w};
#pragma unroll
        for (int e = 0; e < 4; e++) {
            if (vv[e] <= tau) {
                int p = atomicAdd(&s_cnt, 1);
                if (p < BUFCAP) { bval[p] = vv[e]; bidx[p] = jb + e; }
            }
        }
    }
    __syncthreads();
    const int m = (s_cnt < BUFCAP) ? s_cnt : BUFCAP;

    // rank-select: entry e's rank = #{f : (v_f, i_f) < (v_e, i_e)}
    for (int e = tid; e < m; e += 256) {
        float v = bval[e];
        int   j = bidx[e];
        int r = 0;
        for (int t = 0; t < m; t++) {
            float ov = bval[t];
            r += (ov < v) || (ov == v && bidx[t] < j);
        }
        if (r < KCAND) g_cand[row * KCAND + r] = j;
    }
}

// ---------------------------------------------------------------------------
// 3b) authoritative fp32 re-rank of the 16 candidates, replicating the
//     reference arithmetic: dot = single ascending-k fp32 FMA chain,
//     d = (sq_i + sq_j) - 2*dot, tie-break by lower index.
//     One warp per row; lane t owns candidate t.
// ---------------------------------------------------------------------------
__global__ __launch_bounds__(128)
void refine_kernel(const float* __restrict__ x) {
    __shared__ float sxi[4][128];
    const int warp = threadIdx.x >> 5;
    const int lane = threadIdx.x & 31;
    const int row  = blockIdx.x * 4 + warp;

#pragma unroll
    for (int q = 0; q < 4; q++)
        sxi[warp][lane + 32 * q] = x[(size_t)row * C + lane + 32 * q];
    __syncwarp();

    float d = __int_as_float(0x7f800000);
    int   j = 0x7fffffff;
    if (lane < KCAND) {
        j = g_cand[row * KCAND + lane];
        const float* xj = x + (size_t)j * C;
        float acc = 0.f;
#pragma unroll
        for (int k = 0; k < C; k += 4) {
            float4 v = *reinterpret_cast<const float4*>(xj + k);
            acc = fmaf(sxi[warp][k + 0], v.x, acc);
            acc = fmaf(sxi[warp][k + 1], v.y, acc);
            acc = fmaf(sxi[warp][k + 2], v.z, acc);
            acc = fmaf(sxi[warp][k + 3], v.w, acc);
        }
        d = (g_sq[row] + g_sq[j]) - 2.f * acc;
    }

    // lane 0 gathers, sorts by (d, index) with a static bubble network
    float dv[KCAND];
    int   di[KCAND];
#pragma unroll
    for (int t = 0; t < KCAND; t++) {
        dv[t] = __shfl_sync(0xffffffffu, d, t);
        di[t] = __shfl_sync(0xffffffffu, j, t);
    }
    if (lane == 0) {
#pragma unroll
        for (int a = 0; a < KCAND - 1; a++)
#pragma unroll
            for (int bq = 0; bq < KCAND - 1; bq++) {
                bool sw = dv[bq] > dv[bq + 1] ||
                          (dv[bq] == dv[bq + 1] && di[bq] > di[bq + 1]);
                float tv = sw ? dv[bq + 1] : dv[bq];
                dv[bq + 1] = sw ? dv[bq] : dv[bq + 1]; dv[bq] = tv;
                int ti = sw ? di[bq + 1] : di[bq];
                di[bq + 1] = sw ? di[bq] : di[bq + 1]; di[bq] = ti;
            }
#pragma unroll
        for (int t = 0; t < KNN; t++) g_nbr[row * KNN + t] = di[t];
    }
}

// ---------------------------------------------------------------------------
// 4) x2 = x + rel_pos_table[rel], rel[i] = i/128 - i%128 + 127
// ---------------------------------------------------------------------------
__global__ void relpos_kernel(const float* __restrict__ x, const float* __restrict__ tab) {
    int idx = blockIdx.x * blockDim.x + threadIdx.x;   // over N*C
    int i   = idx >> 7;
    int c   = idx & 127;
    int rel = (i >> 7) - (i & 127) + (C - 1);
    g_x2[idx] = x[idx] + tab[(size_t)rel * C + c];
}

// ---------------------------------------------------------------------------
// 5) gather + max-relative + concat-GEMM (+ bias at the end). 16 rows/block.
// ---------------------------------------------------------------------------
__global__ __launch_bounds__(256)
void final_kernel(const float* __restrict__ W, const float* __restrict__ b,
                  float* __restrict__ out) {
    __shared__ float feat[16][260];   // [x2 | m], padded row
    const int r0   = blockIdx.x * 16;
    const int tid  = threadIdx.x;
    const int half = tid >> 7;
    const int c    = tid & 127;
    const float NEGINF = __int_as_float(0xff800000);

#pragma unroll
    for (int rr = 0; rr < 16; rr += 2) {
        int r = rr + half;
        int i = r0 + r;
        float xi = g_x2[(size_t)i * C + c];
        float m  = NEGINF;
#pragma unroll
        for (int k = 0; k < KNN; k++) {
            int j = g_nbr[i * KNN + k];
            m = fmaxf(m, g_x2[(size_t)j * C + c] - xi);
        }
        feat[r][c]     = xi;
        feat[r][C + c] = m;
    }
    __syncthreads();

    const int o = tid;   // output column 0..255
    float acc[16];
#pragma unroll
    for (int r = 0; r < 16; r++) acc[r] = 0.f;

    for (int f = 0; f < 2 * C; f += 4) {
        float w0 = W[(size_t)(f + 0) * COUT + o];
        float w1 = W[(size_t)(f + 1) * COUT + o];
        float w2 = W[(size_t)(f + 2) * COUT + o];
        float w3 = W[(size_t)(f + 3) * COUT + o];
#pragma unroll
        for (int r = 0; r < 16; r++) {
            float4 fv = *reinterpret_cast<const float4*>(&feat[r][f]);
            acc[r] = fmaf(fv.x, w0, acc[r]);
            acc[r] = fmaf(fv.y, w1, acc[r]);
            acc[r] = fmaf(fv.z, w2, acc[r]);
            acc[r] = fmaf(fv.w, w3, acc[r]);
        }
    }
    float bias = b[o];
#pragma unroll
    for (int r = 0; r < 16; r++)
        out[(size_t)(r0 + r) * COUT + o] = acc[r] + bias;
}

// ---------------------------------------------------------------------------
extern "C" void kernel_launch(void* const* d_in, const int* in_sizes, int n_in,
                              void* d_out, int out_size) {
    const float* x   = (const float*)d_in[0];
    const float* tab = (const float*)d_in[1];
    const float* W   = (const float*)d_in[2];
    const float* b   = (const float*)d_in[3];
    float* out = (float*)d_out;
    (void)in_sizes; (void)n_in; (void)out_size;

    sqnorm_kernel<<<(N + 255) / 256, 256>>>(x);
    for (int s = 0; s < NSTRIP; s++) {
        dist_kernel<<<dim3(N / 128, STRIP / 128), 256>>>(x, s * STRIP);
        topk_kernel<<<STRIP, 256>>>(s * STRIP);
    }
    refine_kernel<<<N / 4, 128>>>(x);
    relpos_kernel<<<(N * C) / 256, 256>>>(x, tab);
    final_kernel<<<N / 16, 256>>>(W, b, out);
}

// round 10
// speedup vs baseline: 2.3583x; 1.4500x over previous
#include <cuda_runtime.h>
#include <cstdint>
#include <cstddef>

#define N      16384
#define C      128
#define KNN    9
#define KCAND  16
#define COUT   256
#define STRIP  1024            // 64 MB strip -> L2-resident
#define NSTRIP (N / STRIP)
#define BUFCAP 1024
#define NTILE  (N / 128)       // 128 column tiles
#define SPITCH 36              // smem row pitch in words (16B-aligned rows, conflict-free frags)

// Scratch (static __device__ arrays per harness rules; no cudaMalloc anywhere)
__device__ float g_sq[N];
__device__ float g_dist[(size_t)STRIP * N];     // 64 MB strip, L2-resident
__device__ float g_rowmin[STRIP * NTILE];       // per (strip row, col tile) min
__device__ int   g_cand[N * KCAND];
__device__ int   g_nbr[N * KNN];
__device__ float g_x2[(size_t)N * C];

__device__ __forceinline__ uint32_t f2tf32(float f) {
    uint32_t u;
    asm("cvt.rna.tf32.f32 %0, %1;" : "=r"(u) : "f"(f));
    return u;
}
// monotone float->unsigned key (order-preserving for all finite floats + inf)
__device__ __forceinline__ unsigned fkey(float f) {
    unsigned u = __float_as_uint(f);
    return (u & 0x80000000u) ? ~u : (u | 0x80000000u);
}
__device__ __forceinline__ float funkey(unsigned k) {
    return __uint_as_float((k & 0x80000000u) ? (k & 0x7fffffffu) : ~k);
}

// ---------------------------------------------------------------------------
// 1) squared norms -- replicate an LLVM/XLA vectorized reduce:
//    VF=4, IC=2 -> 8 stride-8 fmaf partial sums, lane-wise combine of the two
//    interleaved vectors, then horizontal tree (l0+l2)+(l1+l3).
// ---------------------------------------------------------------------------
__global__ void sqnorm_kernel(const float* __restrict__ x) {
    int i = blockIdx.x * blockDim.x + threadIdx.x;
    if (i >= N) return;
    const float* r = x + (size_t)i * C;
    float p[8];
#pragma unroll
    for (int l = 0; l < 8; l++) p[l] = 0.f;
#pragma unroll
    for (int k = 0; k < C / 8; k++)
#pragma unroll
        for (int l = 0; l < 8; l++) {
            float v = r[8 * k + l];
            p[l] = fmaf(v, v, p[l]);
        }
    float v0 = p[0] + p[4];
    float v1 = p[1] + p[5];
    float v2 = p[2] + p[6];
    float v3 = p[3] + p[7];
    g_sq[i] = (v0 + v2) + (v1 + v3);
}

// ---------------------------------------------------------------------------
// 2) distance GEMM strip via tf32 tensor-core mma.sync (nomination only --
//    the fp32-exact refine pass below is the ranking authority).
//    Also emits per-(row, 128-col-tile) minima for hierarchical selection.
// ---------------------------------------------------------------------------
__global__ __launch_bounds__(256, 2)
void dist_kernel(const float* __restrict__ x, int row0) {
    __shared__ uint32_t As[128 * SPITCH];   // [m][k] tf32
    __shared__ uint32_t Bs[128 * SPITCH];   // [n][k] tf32
    __shared__ unsigned rmin[128];          // per-row tile-min keys

    const int tid  = threadIdx.x;
    const int warp = tid >> 5;
    const int lane = tid & 31;
    const int g    = lane >> 2;     // groupID
    const int tig  = lane & 3;      // thread-in-group
    const int wm   = warp & 3;      // warp row  (32 rows)
    const int wn   = warp >> 2;     // warp col  (64 cols)
    const int bi   = row0 + blockIdx.y * 128;
    const int bj   = blockIdx.x * 128;

    if (tid < 128) rmin[tid] = 0xFFFFFFFFu;

    float acc[2][8][4];
#pragma unroll
    for (int mt = 0; mt < 2; mt++)
#pragma unroll
        for (int nt = 0; nt < 8; nt++)
#pragma unroll
            for (int e = 0; e < 4; e++) acc[mt][nt][e] = 0.f;

    for (int kc = 0; kc < 4; kc++) {
        // stage 128x32 A and B chunks, rounding to tf32
#pragma unroll
        for (int v = 0; v < 4; v++) {
            int idx = tid + v * 256;         // 0..1023
            int row = idx >> 3;              // 0..127
            int c4  = (idx & 7) << 2;        // 0..28
            float4 a = *reinterpret_cast<const float4*>(&x[(size_t)(bi + row) * C + kc * 32 + c4]);
            uint4 ua = make_uint4(f2tf32(a.x), f2tf32(a.y), f2tf32(a.z), f2tf32(a.w));
            *reinterpret_cast<uint4*>(&As[row * SPITCH + c4]) = ua;
            float4 bb = *reinterpret_cast<const float4*>(&x[(size_t)(bj + row) * C + kc * 32 + c4]);
            uint4 ub = make_uint4(f2tf32(bb.x), f2tf32(bb.y), f2tf32(bb.z), f2tf32(bb.w));
            *reinterpret_cast<uint4*>(&Bs[row * SPITCH + c4]) = ub;
        }
        __syncthreads();

#pragma unroll
        for (int ks = 0; ks < 4; ks++) {
            const int k0 = ks * 8;
            uint32_t a[2][4];
#pragma unroll
            for (int mt = 0; mt < 2; mt++) {
                int rbase = (wm * 32 + mt * 16 + g) * SPITCH + k0 + tig;
                a[mt][0] = As[rbase];
                a[mt][1] = As[rbase + 8 * SPITCH];
                a[mt][2] = As[rbase + 4];
                a[mt][3] = As[rbase + 8 * SPITCH + 4];
            }
            uint32_t b[8][2];
#pragma unroll
            for (int nt = 0; nt < 8; nt++) {
                int cbase = (wn * 64 + nt * 8 + g) * SPITCH + k0 + tig;
                b[nt][0] = Bs[cbase];
                b[nt][1] = Bs[cbase + 4];
            }
#pragma unroll
            for (int mt = 0; mt < 2; mt++)
#pragma unroll
                for (int nt = 0; nt < 8; nt++)
                    asm volatile(
                        "mma.sync.aligned.m16n8k8.row.col.f32.tf32.tf32.f32 "
                        "{%0,%1,%2,%3}, {%4,%5,%6,%7}, {%8,%9}, {%0,%1,%2,%3};"
                        : "+f"(acc[mt][nt][0]), "+f"(acc[mt][nt][1]),
                          "+f"(acc[mt][nt][2]), "+f"(acc[mt][nt][3])
                        : "r"(a[mt][0]), "r"(a[mt][1]), "r"(a[mt][2]), "r"(a[mt][3]),
                          "r"(b[nt][0]), "r"(b[nt][1]));
        }
        __syncthreads();
    }

    const float INFV = __int_as_float(0x7f800000);
#pragma unroll
    for (int mt = 0; mt < 2; mt++) {
        int r_lo = bi + wm * 32 + mt * 16 + g;
        int r_hi = r_lo + 8;
        float si_lo = g_sq[r_lo], si_hi = g_sq[r_hi];
        float mn_lo = INFV, mn_hi = INFV;
#pragma unroll
        for (int nt = 0; nt < 8; nt++) {
            int c0 = bj + wn * 64 + nt * 8 + 2 * tig;
            float sj0 = g_sq[c0], sj1 = g_sq[c0 + 1];
            float d00 = (si_lo + sj0) - 2.f * acc[mt][nt][0];
            float d01 = (si_lo + sj1) - 2.f * acc[mt][nt][1];
            float d10 = (si_hi + sj0) - 2.f * acc[mt][nt][2];
            float d11 = (si_hi + sj1) - 2.f * acc[mt][nt][3];
            if (r_lo == c0)     d00 = INFV;
            if (r_lo == c0 + 1) d01 = INFV;
            if (r_hi == c0)     d10 = INFV;
            if (r_hi == c0 + 1) d11 = INFV;
            mn_lo = fminf(mn_lo, fminf(d00, d01));
            mn_hi = fminf(mn_hi, fminf(d10, d11));
            *reinterpret_cast<float2*>(&g_dist[(size_t)(r_lo - row0) * N + c0]) =
                make_float2(d00, d01);
            *reinterpret_cast<float2*>(&g_dist[(size_t)(r_hi - row0) * N + c0]) =
                make_float2(d10, d11);
        }
        // reduce across tig lanes (same row), then one atomic per row per 8 lanes
        mn_lo = fminf(mn_lo, __shfl_xor_sync(0xffffffffu, mn_lo, 1));
        mn_lo = fminf(mn_lo, __shfl_xor_sync(0xffffffffu, mn_lo, 2));
        mn_hi = fminf(mn_hi, __shfl_xor_sync(0xffffffffu, mn_hi, 1));
        mn_hi = fminf(mn_hi, __shfl_xor_sync(0xffffffffu, mn_hi, 2));
        if (tig == 0) {
            atomicMin(&rmin[wm * 32 + mt * 16 + g],     fkey(mn_lo));
            atomicMin(&rmin[wm * 32 + mt * 16 + g + 8], fkey(mn_hi));
        }
    }
    __syncthreads();
    if (tid < 128)
        g_rowmin[(bi - row0 + tid) * NTILE + blockIdx.x] = funkey(rmin[tid]);
}

// ---------------------------------------------------------------------------
// 3) per-row top-16 via hierarchical tile-min selection.
//    tau = 16th smallest of the 128 tile-minima (each is a distinct element
//    => >=16 elements <= tau). Scan ONLY tiles with min <= tau (~16 of 128),
//    compact elements <= tau, rank-select by (val, idx).
//    Exact same top-16 by (value, index) as a full scan.
// ---------------------------------------------------------------------------
__global__ __launch_bounds__(128)
void topk_kernel(int row0) {
    __shared__ float tmin[NTILE];
    __shared__ float s_tau;
    __shared__ int   s_act[NTILE];
    __shared__ int   s_nact;
    __shared__ int   s_cnt;
    __shared__ float bval[BUFCAP];
    __shared__ int   bidx[BUFCAP];

    const int lrow = blockIdx.x;
    const int row  = row0 + lrow;
    const float* d = g_dist + (size_t)lrow * N;
    const int tid  = threadIdx.x;

    tmin[tid] = g_rowmin[lrow * NTILE + tid];
    if (tid == 0) { s_cnt = 0; s_nact = 0; }
    __syncthreads();

    // tau = tile-min with rank 15 under (val, tile) order
    float mv = tmin[tid];
    int rank = 0;
#pragma unroll 8
    for (int t = 0; t < NTILE; t++) {
        float ov = tmin[t];
        rank += (ov < mv) || (ov == mv && t < tid);
    }
    if (rank == 15) s_tau = mv;
    __syncthreads();
    const float tau = s_tau;

    // active tiles (min <= tau)
    if (tmin[tid] <= tau) {
        int p = atomicAdd(&s_nact, 1);
        s_act[p] = tid;
    }
    __syncthreads();
    const int nact = s_nact;

    // scan active tiles, compact elements <= tau
    for (int a = 0; a < nact; a++) {
        int t = s_act[a];
        float v = d[t * 128 + tid];
        if (v <= tau) {
            int p = atomicAdd(&s_cnt, 1);
            if (p < BUFCAP) { bval[p] = v; bidx[p] = t * 128 + tid; }
        }
    }
    __syncthreads();
    const int m = (s_cnt < BUFCAP) ? s_cnt : BUFCAP;

    // rank-select: entry e's rank = #{f : (v_f, i_f) < (v_e, i_e)}
    for (int e = tid; e < m; e += 128) {
        float v = bval[e];
        int   j = bidx[e];
        int r = 0;
        for (int t = 0; t < m; t++) {
            float ov = bval[t];
            r += (ov < v) || (ov == v && bidx[t] < j);
        }
        if (r < KCAND) g_cand[row * KCAND + r] = j;
    }
}

// ---------------------------------------------------------------------------
// 3b) authoritative fp32 re-rank of the 16 candidates, replicating the
//     reference arithmetic: dot = single ascending-k fp32 FMA chain,
//     d = (sq_i + sq_j) - 2*dot, tie-break by lower index.
//     One warp per row; lane t owns candidate t.
// ---------------------------------------------------------------------------
__global__ __launch_bounds__(128)
void refine_kernel(const float* __restrict__ x) {
    __shared__ float sxi[4][128];
    const int warp = threadIdx.x >> 5;
    const int lane = threadIdx.x & 31;
    const int row  = blockIdx.x * 4 + warp;

#pragma unroll
    for (int q = 0; q < 4; q++)
        sxi[warp][lane + 32 * q] = x[(size_t)row * C + lane + 32 * q];
    __syncwarp();

    float d = __int_as_float(0x7f800000);
    int   j = 0x7fffffff;
    if (lane < KCAND) {
        j = g_cand[row * KCAND + lane];
        const float* xj = x + (size_t)j * C;
        float acc = 0.f;
#pragma unroll
        for (int k = 0; k < C; k += 4) {
            float4 v = *reinterpret_cast<const float4*>(xj + k);
            acc = fmaf(sxi[warp][k + 0], v.x, acc);
            acc = fmaf(sxi[warp][k + 1], v.y, acc);
            acc = fmaf(sxi[warp][k + 2], v.z, acc);
            acc = fmaf(sxi[warp][k + 3], v.w, acc);
        }
        d = (g_sq[row] + g_sq[j]) - 2.f * acc;
    }

    // lane 0 gathers, sorts by (d, index) with a static bubble network
    float dv[KCAND];
    int   di[KCAND];
#pragma unroll
    for (int t = 0; t < KCAND; t++) {
        dv[t] = __shfl_sync(0xffffffffu, d, t);
        di[t] = __shfl_sync(0xffffffffu, j, t);
    }
    if (lane == 0) {
#pragma unroll
        for (int a = 0; a < KCAND - 1; a++)
#pragma unroll
            for (int bq = 0; bq < KCAND - 1; bq++) {
                bool sw = dv[bq] > dv[bq + 1] ||
                          (dv[bq] == dv[bq + 1] && di[bq] > di[bq + 1]);
                float tv = sw ? dv[bq + 1] : dv[bq];
                dv[bq + 1] = sw ? dv[bq] : dv[bq + 1]; dv[bq] = tv;
                int ti = sw ? di[bq + 1] : di[bq];
                di[bq + 1] = sw ? di[bq] : di[bq + 1]; di[bq] = ti;
            }
#pragma unroll
        for (int t = 0; t < KNN; t++) g_nbr[row * KNN + t] = di[t];
    }
}

// ---------------------------------------------------------------------------
// 4) x2 = x + rel_pos_table[rel], rel[i] = i/128 - i%128 + 127
// ---------------------------------------------------------------------------
__global__ void relpos_kernel(const float* __restrict__ x, const float* __restrict__ tab) {
    int idx = blockIdx.x * blockDim.x + threadIdx.x;   // over N*C
    int i   = idx >> 7;
    int c   = idx & 127;
    int rel = (i >> 7) - (i & 127) + (C - 1);
    g_x2[idx] = x[idx] + tab[(size_t)rel * C + c];
}

// ---------------------------------------------------------------------------
// 5) gather + max-relative + concat-GEMM (+ bias at the end). 16 rows/block.
// ---------------------------------------------------------------------------
__global__ __launch_bounds__(256)
void final_kernel(const float* __restrict__ W, const float* __restrict__ b,
                  float* __restrict__ out) {
    __shared__ float feat[16][260];   // [x2 | m], padded row
    const int r0   = blockIdx.x * 16;
    const int tid  = threadIdx.x;
    const int half = tid >> 7;
    const int c    = tid & 127;
    const float NEGINF = __int_as_float(0xff800000);

#pragma unroll
    for (int rr = 0; rr < 16; rr += 2) {
        int r = rr + half;
        int i = r0 + r;
        float xi = g_x2[(size_t)i * C + c];
        float m  = NEGINF;
#pragma unroll
        for (int k = 0; k < KNN; k++) {
            int j = g_nbr[i * KNN + k];
            m = fmaxf(m, g_x2[(size_t)j * C + c] - xi);
        }
        feat[r][c]     = xi;
        feat[r][C + c] = m;
    }
    __syncthreads();

    const int o = tid;   // output column 0..255
    float acc[16];
#pragma unroll
    for (int r = 0; r < 16; r++) acc[r] = 0.f;

    for (int f = 0; f < 2 * C; f += 4) {
        float w0 = W[(size_t)(f + 0) * COUT + o];
        float w1 = W[(size_t)(f + 1) * COUT + o];
        float w2 = W[(size_t)(f + 2) * COUT + o];
        float w3 = W[(size_t)(f + 3) * COUT + o];
#pragma unroll
        for (int r = 0; r < 16; r++) {
            float4 fv = *reinterpret_cast<const float4*>(&feat[r][f]);
            acc[r] = fmaf(fv.x, w0, acc[r]);
            acc[r] = fmaf(fv.y, w1, acc[r]);
            acc[r] = fmaf(fv.z, w2, acc[r]);
            acc[r] = fmaf(fv.w, w3, acc[r]);
        }
    }
    float bias = b[o];
#pragma unroll
    for (int r = 0; r < 16; r++)
        out[(size_t)(r0 + r) * COUT + o] = acc[r] + bias;
}

// ---------------------------------------------------------------------------
extern "C" void kernel_launch(void* const* d_in, const int* in_sizes, int n_in,
                              void* d_out, int out_size) {
    const float* x   = (const float*)d_in[0];
    const float* tab = (const float*)d_in[1];
    const float* W   = (const float*)d_in[2];
    const float* b   = (const float*)d_in[3];
    float* out = (float*)d_out;
    (void)in_sizes; (void)n_in; (void)out_size;

    sqnorm_kernel<<<(N + 255) / 256, 256>>>(x);
    for (int s = 0; s < NSTRIP; s++) {
        dist_kernel<<<dim3(N / 128, STRIP / 128), 256>>>(x, s * STRIP);
        topk_kernel<<<STRIP, 128>>>(s * STRIP);
    }
    refine_kernel<<<N / 4, 128>>>(x);
    relpos_kernel<<<(N * C) / 256, 256>>>(x, tab);
    final_kernel<<<N / 16, 256>>>(W, b, out);
}

// round 11
// speedup vs baseline: 2.8471x; 1.2073x over previous
#include <cuda_runtime.h>
#include <cstdint>
#include <cstddef>

#define N      16384
#define C      128
#define KNN    9
#define KCAND  16
#define COUT   256
#define BUFCAP 1024
#define NTILE  (N / 128)       // 128 column tiles
#define SPITCH 36              // smem row pitch in words
#define CHWORDS (128 * SPITCH) // words per 128x32 chunk buffer

// Scratch (static __device__ arrays per harness rules; no cudaMalloc anywhere)
__device__ float g_sq[N];
__device__ float g_dist[(size_t)N * N];        // full 1 GiB distance matrix
__device__ float g_rowmin[N * NTILE];          // per (row, col tile) min
__device__ int   g_cand[N * KCAND];
__device__ int   g_nbr[N * KNN];
__device__ float g_x2[(size_t)N * C];

__device__ __forceinline__ uint32_t f2tf32(float f) {
    uint32_t u;
    asm("cvt.rna.tf32.f32 %0, %1;" : "=r"(u) : "f"(f));
    return u;
}
// monotone float->unsigned key (order-preserving for all finite floats + inf)
__device__ __forceinline__ unsigned fkey(float f) {
    unsigned u = __float_as_uint(f);
    return (u & 0x80000000u) ? ~u : (u | 0x80000000u);
}
__device__ __forceinline__ float funkey(unsigned k) {
    return __uint_as_float((k & 0x80000000u) ? (k & 0x7fffffffu) : ~k);
}

// ---------------------------------------------------------------------------
// 1) squared norms -- replicate an LLVM/XLA vectorized reduce.
// ---------------------------------------------------------------------------
__global__ void sqnorm_kernel(const float* __restrict__ x) {
    int i = blockIdx.x * blockDim.x + threadIdx.x;
    if (i >= N) return;
    const float* r = x + (size_t)i * C;
    float p[8];
#pragma unroll
    for (int l = 0; l < 8; l++) p[l] = 0.f;
#pragma unroll
    for (int k = 0; k < C / 8; k++)
#pragma unroll
        for (int l = 0; l < 8; l++) {
            float v = r[8 * k + l];
            p[l] = fmaf(v, v, p[l]);
        }
    float v0 = p[0] + p[4];
    float v1 = p[1] + p[5];
    float v2 = p[2] + p[6];
    float v3 = p[3] + p[7];
    g_sq[i] = (v0 + v2) + (v1 + v3);
}

// ---------------------------------------------------------------------------
// 2) MONOLITHIC distance GEMM via tf32 mma.sync with cp.async double-buffered
//    staging (nomination only -- fp32-exact refine is the ranking authority).
//    Emits dist tile + per-(row, tile) minima.
// ---------------------------------------------------------------------------
__device__ __forceinline__ void stage_chunk(const float* __restrict__ x,
                                            int bi, int bj, int kc,
                                            float* As, float* Bs, int tid) {
#pragma unroll
    for (int v = 0; v < 4; v++) {
        int idx = tid + v * 256;         // 0..1023
        int row = idx >> 3;              // 0..127
        int c4  = (idx & 7) << 2;        // 0..28
        const float* ga = &x[(size_t)(bi + row) * C + kc * 32 + c4];
        unsigned da = (unsigned)__cvta_generic_to_shared(&As[row * SPITCH + c4]);
        asm volatile("cp.async.cg.shared.global [%0], [%1], 16;" :: "r"(da), "l"(ga));
        const float* gb = &x[(size_t)(bj + row) * C + kc * 32 + c4];
        unsigned db = (unsigned)__cvta_generic_to_shared(&Bs[row * SPITCH + c4]);
        asm volatile("cp.async.cg.shared.global [%0], [%1], 16;" :: "r"(db), "l"(gb));
    }
}

__global__ __launch_bounds__(256, 2)
void dist_kernel(const float* __restrict__ x) {
    extern __shared__ float sm[];
    float* Abuf[2] = { sm,               sm + 2 * CHWORDS };
    float* Bbuf[2] = { sm + CHWORDS,     sm + 3 * CHWORDS };
    unsigned* rmin = (unsigned*)(sm + 4 * CHWORDS);

    const int tid  = threadIdx.x;
    const int warp = tid >> 5;
    const int lane = tid & 31;
    const int g    = lane >> 2;     // groupID
    const int tig  = lane & 3;      // thread-in-group
    const int wm   = warp & 3;      // warp row  (32 rows)
    const int wn   = warp >> 2;     // warp col  (64 cols)
    const int bi   = blockIdx.y * 128;
    const int bj   = blockIdx.x * 128;

    if (tid < 128) rmin[tid] = 0xFFFFFFFFu;

    float acc[2][8][4];
#pragma unroll
    for (int mt = 0; mt < 2; mt++)
#pragma unroll
        for (int nt = 0; nt < 8; nt++)
#pragma unroll
            for (int e = 0; e < 4; e++) acc[mt][nt][e] = 0.f;

    stage_chunk(x, bi, bj, 0, Abuf[0], Bbuf[0], tid);
    asm volatile("cp.async.commit_group;");

#pragma unroll
    for (int kc = 0; kc < 4; kc++) {
        if (kc < 3) {
            stage_chunk(x, bi, bj, kc + 1, Abuf[(kc + 1) & 1], Bbuf[(kc + 1) & 1], tid);
            asm volatile("cp.async.commit_group;");
            asm volatile("cp.async.wait_group 1;");
        } else {
            asm volatile("cp.async.wait_group 0;");
        }
        __syncthreads();

        const float* As = Abuf[kc & 1];
        const float* Bs = Bbuf[kc & 1];
#pragma unroll
        for (int ks = 0; ks < 4; ks++) {
            const int k0 = ks * 8;
            uint32_t a[2][4];
#pragma unroll
            for (int mt = 0; mt < 2; mt++) {
                int rbase = (wm * 32 + mt * 16 + g) * SPITCH + k0 + tig;
                a[mt][0] = f2tf32(As[rbase]);
                a[mt][1] = f2tf32(As[rbase + 8 * SPITCH]);
                a[mt][2] = f2tf32(As[rbase + 4]);
                a[mt][3] = f2tf32(As[rbase + 8 * SPITCH + 4]);
            }
            uint32_t b[8][2];
#pragma unroll
            for (int nt = 0; nt < 8; nt++) {
                int cbase = (wn * 64 + nt * 8 + g) * SPITCH + k0 + tig;
                b[nt][0] = f2tf32(Bs[cbase]);
                b[nt][1] = f2tf32(Bs[cbase + 4]);
            }
#pragma unroll
            for (int mt = 0; mt < 2; mt++)
#pragma unroll
                for (int nt = 0; nt < 8; nt++)
                    asm volatile(
                        "mma.sync.aligned.m16n8k8.row.col.f32.tf32.tf32.f32 "
                        "{%0,%1,%2,%3}, {%4,%5,%6,%7}, {%8,%9}, {%0,%1,%2,%3};"
                        : "+f"(acc[mt][nt][0]), "+f"(acc[mt][nt][1]),
                          "+f"(acc[mt][nt][2]), "+f"(acc[mt][nt][3])
                        : "r"(a[mt][0]), "r"(a[mt][1]), "r"(a[mt][2]), "r"(a[mt][3]),
                          "r"(b[nt][0]), "r"(b[nt][1]));
        }
        __syncthreads();
    }

    const float INFV = __int_as_float(0x7f800000);
#pragma unroll
    for (int mt = 0; mt < 2; mt++) {
        int r_lo = bi + wm * 32 + mt * 16 + g;
        int r_hi = r_lo + 8;
        float si_lo = g_sq[r_lo], si_hi = g_sq[r_hi];
        float mn_lo = INFV, mn_hi = INFV;
#pragma unroll
        for (int nt = 0; nt < 8; nt++) {
            int c0 = bj + wn * 64 + nt * 8 + 2 * tig;
            float sj0 = g_sq[c0], sj1 = g_sq[c0 + 1];
            float d00 = (si_lo + sj0) - 2.f * acc[mt][nt][0];
            float d01 = (si_lo + sj1) - 2.f * acc[mt][nt][1];
            float d10 = (si_hi + sj0) - 2.f * acc[mt][nt][2];
            float d11 = (si_hi + sj1) - 2.f * acc[mt][nt][3];
            if (r_lo == c0)     d00 = INFV;
            if (r_lo == c0 + 1) d01 = INFV;
            if (r_hi == c0)     d10 = INFV;
            if (r_hi == c0 + 1) d11 = INFV;
            mn_lo = fminf(mn_lo, fminf(d00, d01));
            mn_hi = fminf(mn_hi, fminf(d10, d11));
            *reinterpret_cast<float2*>(&g_dist[(size_t)r_lo * N + c0]) =
                make_float2(d00, d01);
            *reinterpret_cast<float2*>(&g_dist[(size_t)r_hi * N + c0]) =
                make_float2(d10, d11);
        }
        mn_lo = fminf(mn_lo, __shfl_xor_sync(0xffffffffu, mn_lo, 1));
        mn_lo = fminf(mn_lo, __shfl_xor_sync(0xffffffffu, mn_lo, 2));
        mn_hi = fminf(mn_hi, __shfl_xor_sync(0xffffffffu, mn_hi, 1));
        mn_hi = fminf(mn_hi, __shfl_xor_sync(0xffffffffu, mn_hi, 2));
        if (tig == 0) {
            atomicMin(&rmin[wm * 32 + mt * 16 + g],     fkey(mn_lo));
            atomicMin(&rmin[wm * 32 + mt * 16 + g + 8], fkey(mn_hi));
        }
    }
    __syncthreads();
    if (tid < 128)
        g_rowmin[(bi + tid) * NTILE + blockIdx.x] = funkey(rmin[tid]);
}

// ---------------------------------------------------------------------------
// 3) per-row top-16 via hierarchical tile-min selection (exact by (val,idx)).
// ---------------------------------------------------------------------------
__global__ __launch_bounds__(128)
void topk_kernel() {
    __shared__ float tmin[NTILE];
    __shared__ float s_tau;
    __shared__ int   s_act[NTILE];
    __shared__ int   s_nact;
    __shared__ int   s_cnt;
    __shared__ float bval[BUFCAP];
    __shared__ int   bidx[BUFCAP];

    const int row  = blockIdx.x;
    const float* d = g_dist + (size_t)row * N;
    const int tid  = threadIdx.x;

    tmin[tid] = g_rowmin[row * NTILE + tid];
    if (tid == 0) { s_cnt = 0; s_nact = 0; }
    __syncthreads();

    // tau = tile-min with rank 15 under (val, tile) order
    float mv = tmin[tid];
    int rank = 0;
#pragma unroll 8
    for (int t = 0; t < NTILE; t++) {
        float ov = tmin[t];
        rank += (ov < mv) || (ov == mv && t < tid);
    }
    if (rank == 15) s_tau = mv;
    __syncthreads();
    const float tau = s_tau;

    // active tiles (min <= tau)
    if (tmin[tid] <= tau) {
        int p = atomicAdd(&s_nact, 1);
        s_act[p] = tid;
    }
    __syncthreads();
    const int nact = s_nact;

    // scan active tiles, compact elements <= tau
    for (int a = 0; a < nact; a++) {
        int t = s_act[a];
        float v = d[t * 128 + tid];
        if (v <= tau) {
            int p = atomicAdd(&s_cnt, 1);
            if (p < BUFCAP) { bval[p] = v; bidx[p] = t * 128 + tid; }
        }
    }
    __syncthreads();
    const int m = (s_cnt < BUFCAP) ? s_cnt : BUFCAP;

    // rank-select: entry e's rank = #{f : (v_f, i_f) < (v_e, i_e)}
    for (int e = tid; e < m; e += 128) {
        float v = bval[e];
        int   j = bidx[e];
        int r = 0;
        for (int t = 0; t < m; t++) {
            float ov = bval[t];
            r += (ov < v) || (ov == v && bidx[t] < j);
        }
        if (r < KCAND) g_cand[row * KCAND + r] = j;
    }
}

// ---------------------------------------------------------------------------
// 3b) authoritative fp32 re-rank of the 16 candidates (reference arithmetic).
// ---------------------------------------------------------------------------
__global__ __launch_bounds__(128)
void refine_kernel(const float* __restrict__ x) {
    __shared__ float sxi[4][128];
    const int warp = threadIdx.x >> 5;
    const int lane = threadIdx.x & 31;
    const int row  = blockIdx.x * 4 + warp;

#pragma unroll
    for (int q = 0; q < 4; q++)
        sxi[warp][lane + 32 * q] = x[(size_t)row * C + lane + 32 * q];
    __syncwarp();

    float d = __int_as_float(0x7f800000);
    int   j = 0x7fffffff;
    if (lane < KCAND) {
        j = g_cand[row * KCAND + lane];
        const float* xj = x + (size_t)j * C;
        float acc = 0.f;
#pragma unroll
        for (int k = 0; k < C; k += 4) {
            float4 v = *reinterpret_cast<const float4*>(xj + k);
            acc = fmaf(sxi[warp][k + 0], v.x, acc);
            acc = fmaf(sxi[warp][k + 1], v.y, acc);
            acc = fmaf(sxi[warp][k + 2], v.z, acc);
            acc = fmaf(sxi[warp][k + 3], v.w, acc);
        }
        d = (g_sq[row] + g_sq[j]) - 2.f * acc;
    }

    float dv[KCAND];
    int   di[KCAND];
#pragma unroll
    for (int t = 0; t < KCAND; t++) {
        dv[t] = __shfl_sync(0xffffffffu, d, t);
        di[t] = __shfl_sync(0xffffffffu, j, t);
    }
    if (lane == 0) {
#pragma unroll
        for (int a = 0; a < KCAND - 1; a++)
#pragma unroll
            for (int bq = 0; bq < KCAND - 1; bq++) {
                bool sw = dv[bq] > dv[bq + 1] ||
                          (dv[bq] == dv[bq + 1] && di[bq] > di[bq + 1]);
                float tv = sw ? dv[bq + 1] : dv[bq];
                dv[bq + 1] = sw ? dv[bq] : dv[bq + 1]; dv[bq] = tv;
                int ti = sw ? di[bq + 1] : di[bq];
                di[bq + 1] = sw ? di[bq] : di[bq + 1]; di[bq] = ti;
            }
#pragma unroll
        for (int t = 0; t < KNN; t++) g_nbr[row * KNN + t] = di[t];
    }
}

// ---------------------------------------------------------------------------
// 4) x2 = x + rel_pos_table[rel]
// ---------------------------------------------------------------------------
__global__ void relpos_kernel(const float* __restrict__ x, const float* __restrict__ tab) {
    int idx = blockIdx.x * blockDim.x + threadIdx.x;
    int i   = idx >> 7;
    int c   = idx & 127;
    int rel = (i >> 7) - (i & 127) + (C - 1);
    g_x2[idx] = x[idx] + tab[(size_t)rel * C + c];
}

// ---------------------------------------------------------------------------
// 5) gather + max-relative + concat-GEMM (+ bias at the end). 16 rows/block.
// ---------------------------------------------------------------------------
__global__ __launch_bounds__(256)
void final_kernel(const float* __restrict__ W, const float* __restrict__ b,
                  float* __restrict__ out) {
    __shared__ float feat[16][260];
    const int r0   = blockIdx.x * 16;
    const int tid  = threadIdx.x;
    const int half = tid >> 7;
    const int c    = tid & 127;
    const float NEGINF = __int_as_float(0xff800000);

#pragma unroll
    for (int rr = 0; rr < 16; rr += 2) {
        int r = rr + half;
        int i = r0 + r;
        float xi = g_x2[(size_t)i * C + c];
        float m  = NEGINF;
#pragma unroll
        for (int k = 0; k < KNN; k++) {
            int j = g_nbr[i * KNN + k];
            m = fmaxf(m, g_x2[(size_t)j * C + c] - xi);
        }
        feat[r][c]     = xi;
        feat[r][C + c] = m;
    }
    __syncthreads();

    const int o = tid;
    float acc[16];
#pragma unroll
    for (int r = 0; r < 16; r++) acc[r] = 0.f;

    for (int f = 0; f < 2 * C; f += 4) {
        float w0 = W[(size_t)(f + 0) * COUT + o];
        float w1 = W[(size_t)(f + 1) * COUT + o];
        float w2 = W[(size_t)(f + 2) * COUT + o];
        float w3 = W[(size_t)(f + 3) * COUT + o];
#pragma unroll
        for (int r = 0; r < 16; r++) {
            float4 fv = *reinterpret_cast<const float4*>(&feat[r][f]);
            acc[r] = fmaf(fv.x, w0, acc[r]);
            acc[r] = fmaf(fv.y, w1, acc[r]);
            acc[r] = fmaf(fv.z, w2, acc[r]);
            acc[r] = fmaf(fv.w, w3, acc[r]);
        }
    }
    float bias = b[o];
#pragma unroll
    for (int r = 0; r < 16; r++)
        out[(size_t)(r0 + r) * COUT + o] = acc[r] + bias;
}

// ---------------------------------------------------------------------------
extern "C" void kernel_launch(void* const* d_in, const int* in_sizes, int n_in,
                              void* d_out, int out_size) {
    const float* x   = (const float*)d_in[0];
    const float* tab = (const float*)d_in[1];
    const float* W   = (const float*)d_in[2];
    const float* b   = (const float*)d_in[3];
    float* out = (float*)d_out;
    (void)in_sizes; (void)n_in; (void)out_size;

    const int smem_bytes = (4 * CHWORDS) * (int)sizeof(float) + 128 * (int)sizeof(unsigned);
    static bool attr_set = false;
    if (!attr_set) {
        cudaFuncSetAttribute(dist_kernel,
                             cudaFuncAttributeMaxDynamicSharedMemorySize, smem_bytes);
        attr_set = true;
    }

    sqnorm_kernel<<<(N + 255) / 256, 256>>>(x);
    dist_kernel<<<dim3(NTILE, NTILE), 256, smem_bytes>>>(x);
    topk_kernel<<<N, 128>>>();
    refine_kernel<<<N / 4, 128>>>(x);
    relpos_kernel<<<(N * C) / 256, 256>>>(x, tab);
    final_kernel<<<N / 16, 256>>>(W, b, out);
}

// round 12
// speedup vs baseline: 3.4676x; 1.2179x over previous
#include <cuda_runtime.h>
#include <cstdint>
#include <cstddef>

#define N      16384
#define C      128
#define KNN    9
#define KCAND  16
#define COUT   256
#define BUFCAP 1024
#define NTILE  (N / 128)       // 128 column tiles
#define SPITCH 36              // smem row pitch in words
#define CHWORDS (128 * SPITCH) // words per 128x32 chunk buffer
#define TPITCH 132             // transpose buffer pitch (words)

// Scratch (static __device__ arrays per harness rules; no cudaMalloc anywhere)
__device__ float g_sq[N];
__device__ float g_dist[(size_t)N * N];        // full 1 GiB distance matrix
__device__ float g_rowmin[N * NTILE];          // per (row, col tile) min
__device__ int   g_cand[N * KCAND];
__device__ int   g_nbr[N * KNN];
__device__ float g_x2[(size_t)N * C];

__device__ __forceinline__ uint32_t f2tf32(float f) {
    uint32_t u;
    asm("cvt.rna.tf32.f32 %0, %1;" : "=r"(u) : "f"(f));
    return u;
}
// monotone float->unsigned key (order-preserving for all finite floats + inf)
__device__ __forceinline__ unsigned fkey(float f) {
    unsigned u = __float_as_uint(f);
    return (u & 0x80000000u) ? ~u : (u | 0x80000000u);
}
__device__ __forceinline__ float funkey(unsigned k) {
    return __uint_as_float((k & 0x80000000u) ? (k & 0x7fffffffu) : ~k);
}

// ---------------------------------------------------------------------------
// 1) squared norms -- replicate an LLVM/XLA vectorized reduce.
// ---------------------------------------------------------------------------
__global__ void sqnorm_kernel(const float* __restrict__ x) {
    int i = blockIdx.x * blockDim.x + threadIdx.x;
    if (i >= N) return;
    const float* r = x + (size_t)i * C;
    float p[8];
#pragma unroll
    for (int l = 0; l < 8; l++) p[l] = 0.f;
#pragma unroll
    for (int k = 0; k < C / 8; k++)
#pragma unroll
        for (int l = 0; l < 8; l++) {
            float v = r[8 * k + l];
            p[l] = fmaf(v, v, p[l]);
        }
    float v0 = p[0] + p[4];
    float v1 = p[1] + p[5];
    float v2 = p[2] + p[6];
    float v3 = p[3] + p[7];
    g_sq[i] = (v0 + v2) + (v1 + v3);
}

// ---------------------------------------------------------------------------
// 2) SYMMETRIC monolithic distance GEMM (tf32 mma.sync, cp.async pipelined).
//    Only upper-triangle tiles (tileY <= tileX) compute; off-diagonal tiles
//    also emit the mirrored tile (smem transpose) + per-column minima.
// ---------------------------------------------------------------------------
__device__ __forceinline__ void stage_chunk(const float* __restrict__ x,
                                            int bi, int bj, int kc,
                                            float* As, float* Bs, int tid) {
#pragma unroll
    for (int v = 0; v < 4; v++) {
        int idx = tid + v * 256;         // 0..1023
        int row = idx >> 3;              // 0..127
        int c4  = (idx & 7) << 2;        // 0..28
        const float* ga = &x[(size_t)(bi + row) * C + kc * 32 + c4];
        unsigned da = (unsigned)__cvta_generic_to_shared(&As[row * SPITCH + c4]);
        asm volatile("cp.async.cg.shared.global [%0], [%1], 16;" :: "r"(da), "l"(ga));
        const float* gb = &x[(size_t)(bj + row) * C + kc * 32 + c4];
        unsigned db = (unsigned)__cvta_generic_to_shared(&Bs[row * SPITCH + c4]);
        asm volatile("cp.async.cg.shared.global [%0], [%1], 16;" :: "r"(db), "l"(gb));
    }
}

__global__ __launch_bounds__(256, 2)
void dist_kernel(const float* __restrict__ x) {
    if (blockIdx.y > blockIdx.x) return;   // lower-triangle tiles mirrored

    extern __shared__ float sm[];
    float* Abuf[2] = { sm,               sm + 2 * CHWORDS };
    float* Bbuf[2] = { sm + CHWORDS,     sm + 3 * CHWORDS };
    unsigned* rmin = (unsigned*)(sm + 4 * CHWORDS);
    unsigned* cmin = rmin + 128;

    const int tid  = threadIdx.x;
    const int warp = tid >> 5;
    const int lane = tid & 31;
    const int g    = lane >> 2;     // groupID
    const int tig  = lane & 3;      // thread-in-group
    const int wm   = warp & 3;      // warp row  (32 rows)
    const int wn   = warp >> 2;     // warp col  (64 cols)
    const int bi   = blockIdx.y * 128;
    const int bj   = blockIdx.x * 128;
    const bool mirror = (bi != bj);

    if (tid < 128) { rmin[tid] = 0xFFFFFFFFu; cmin[tid] = 0xFFFFFFFFu; }

    float acc[2][8][4];
#pragma unroll
    for (int mt = 0; mt < 2; mt++)
#pragma unroll
        for (int nt = 0; nt < 8; nt++)
#pragma unroll
            for (int e = 0; e < 4; e++) acc[mt][nt][e] = 0.f;

    stage_chunk(x, bi, bj, 0, Abuf[0], Bbuf[0], tid);
    asm volatile("cp.async.commit_group;");

#pragma unroll
    for (int kc = 0; kc < 4; kc++) {
        if (kc < 3) {
            stage_chunk(x, bi, bj, kc + 1, Abuf[(kc + 1) & 1], Bbuf[(kc + 1) & 1], tid);
            asm volatile("cp.async.commit_group;");
            asm volatile("cp.async.wait_group 1;");
        } else {
            asm volatile("cp.async.wait_group 0;");
        }
        __syncthreads();

        const float* As = Abuf[kc & 1];
        const float* Bs = Bbuf[kc & 1];
#pragma unroll
        for (int ks = 0; ks < 4; ks++) {
            const int k0 = ks * 8;
            uint32_t a[2][4];
#pragma unroll
            for (int mt = 0; mt < 2; mt++) {
                int rbase = (wm * 32 + mt * 16 + g) * SPITCH + k0 + tig;
                a[mt][0] = f2tf32(As[rbase]);
                a[mt][1] = f2tf32(As[rbase + 8 * SPITCH]);
                a[mt][2] = f2tf32(As[rbase + 4]);
                a[mt][3] = f2tf32(As[rbase + 8 * SPITCH + 4]);
            }
            uint32_t b[8][2];
#pragma unroll
            for (int nt = 0; nt < 8; nt++) {
                int cbase = (wn * 64 + nt * 8 + g) * SPITCH + k0 + tig;
                b[nt][0] = f2tf32(Bs[cbase]);
                b[nt][1] = f2tf32(Bs[cbase + 4]);
            }
#pragma unroll
            for (int mt = 0; mt < 2; mt++)
#pragma unroll
                for (int nt = 0; nt < 8; nt++)
                    asm volatile(
                        "mma.sync.aligned.m16n8k8.row.col.f32.tf32.tf32.f32 "
                        "{%0,%1,%2,%3}, {%4,%5,%6,%7}, {%8,%9}, {%0,%1,%2,%3};"
                        : "+f"(acc[mt][nt][0]), "+f"(acc[mt][nt][1]),
                          "+f"(acc[mt][nt][2]), "+f"(acc[mt][nt][3])
                        : "r"(a[mt][0]), "r"(a[mt][1]), "r"(a[mt][2]), "r"(a[mt][3]),
                          "r"(b[nt][0]), "r"(b[nt][1]));
        }
        __syncthreads();
    }
    // staging smem is free from here on (reused as transpose buffer)

    const float INFV = __int_as_float(0x7f800000);
    float cm[8][2];
#pragma unroll
    for (int nt = 0; nt < 8; nt++) { cm[nt][0] = INFV; cm[nt][1] = INFV; }

#pragma unroll
    for (int mt = 0; mt < 2; mt++) {
        int rl = wm * 32 + mt * 16 + g;        // local row (lo); hi = +8
        int r_lo = bi + rl, r_hi = r_lo + 8;
        float si_lo = g_sq[r_lo], si_hi = g_sq[r_hi];
        float mn_lo = INFV, mn_hi = INFV;
#pragma unroll
        for (int nt = 0; nt < 8; nt++) {
            int cl = wn * 64 + nt * 8 + 2 * tig;   // local col
            int c0 = bj + cl;
            float sj0 = g_sq[c0], sj1 = g_sq[c0 + 1];
            float d00 = (si_lo + sj0) - 2.f * acc[mt][nt][0];
            float d01 = (si_lo + sj1) - 2.f * acc[mt][nt][1];
            float d10 = (si_hi + sj0) - 2.f * acc[mt][nt][2];
            float d11 = (si_hi + sj1) - 2.f * acc[mt][nt][3];
            if (r_lo == c0)     d00 = INFV;
            if (r_lo == c0 + 1) d01 = INFV;
            if (r_hi == c0)     d10 = INFV;
            if (r_hi == c0 + 1) d11 = INFV;
            mn_lo = fminf(mn_lo, fminf(d00, d01));
            mn_hi = fminf(mn_hi, fminf(d10, d11));
            *reinterpret_cast<float2*>(&g_dist[(size_t)r_lo * N + c0]) =
                make_float2(d00, d01);
            *reinterpret_cast<float2*>(&g_dist[(size_t)r_hi * N + c0]) =
                make_float2(d10, d11);
            if (mirror) {
                cm[nt][0] = fminf(cm[nt][0], fminf(d00, d10));
                cm[nt][1] = fminf(cm[nt][1], fminf(d01, d11));
                sm[cl * TPITCH + rl]           = d00;
                sm[(cl + 1) * TPITCH + rl]     = d01;
                sm[cl * TPITCH + rl + 8]       = d10;
                sm[(cl + 1) * TPITCH + rl + 8] = d11;
            }
        }
        mn_lo = fminf(mn_lo, __shfl_xor_sync(0xffffffffu, mn_lo, 1));
        mn_lo = fminf(mn_lo, __shfl_xor_sync(0xffffffffu, mn_lo, 2));
        mn_hi = fminf(mn_hi, __shfl_xor_sync(0xffffffffu, mn_hi, 1));
        mn_hi = fminf(mn_hi, __shfl_xor_sync(0xffffffffu, mn_hi, 2));
        if (tig == 0) {
            atomicMin(&rmin[wm * 32 + mt * 16 + g],     fkey(mn_lo));
            atomicMin(&rmin[wm * 32 + mt * 16 + g + 8], fkey(mn_hi));
        }
    }

    if (mirror) {
        // column minima: reduce over g lanes (bits 2..4), then shared atomics
#pragma unroll
        for (int nt = 0; nt < 8; nt++)
#pragma unroll
            for (int e = 0; e < 2; e++) {
                float v = cm[nt][e];
                v = fminf(v, __shfl_xor_sync(0xffffffffu, v, 4));
                v = fminf(v, __shfl_xor_sync(0xffffffffu, v, 8));
                v = fminf(v, __shfl_xor_sync(0xffffffffu, v, 16));
                if (lane < 4)
                    atomicMin(&cmin[wn * 64 + nt * 8 + 2 * tig + e], fkey(v));
            }
    }
    __syncthreads();

    if (tid < 128)
        g_rowmin[(bi + tid) * NTILE + blockIdx.x] = funkey(rmin[tid]);

    if (mirror) {
        // coalesced mirrored-tile store: row tr of T = column tr of the tile
#pragma unroll
        for (int it = 0; it < 16; it++) {
            int idx = tid + it * 256;     // 0..4095
            int tr  = idx >> 5;           // 0..127
            int c4  = (idx & 31) << 2;    // 0..124
            float4 v = *reinterpret_cast<const float4*>(&sm[tr * TPITCH + c4]);
            *reinterpret_cast<float4*>(&g_dist[(size_t)(bj + tr) * N + bi + c4]) = v;
        }
        if (tid < 128)
            g_rowmin[(bj + tid) * NTILE + blockIdx.y] = funkey(cmin[tid]);
    }
}

// ---------------------------------------------------------------------------
// 3) per-row top-16 via hierarchical tile-min selection (exact by (val,idx)).
// ---------------------------------------------------------------------------
__global__ __launch_bounds__(128)
void topk_kernel() {
    __shared__ float tmin[NTILE];
    __shared__ float s_tau;
    __shared__ int   s_act[NTILE];
    __shared__ int   s_nact;
    __shared__ int   s_cnt;
    __shared__ float bval[BUFCAP];
    __shared__ int   bidx[BUFCAP];

    const int row  = blockIdx.x;
    const float* d = g_dist + (size_t)row * N;
    const int tid  = threadIdx.x;

    tmin[tid] = g_rowmin[row * NTILE + tid];
    if (tid == 0) { s_cnt = 0; s_nact = 0; }
    __syncthreads();

    // tau = tile-min with rank 15 under (val, tile) order
    float mv = tmin[tid];
    int rank = 0;
#pragma unroll 8
    for (int t = 0; t < NTILE; t++) {
        float ov = tmin[t];
        rank += (ov < mv) || (ov == mv && t < tid);
    }
    if (rank == 15) s_tau = mv;
    __syncthreads();
    const float tau = s_tau;

    // active tiles (min <= tau)
    if (tmin[tid] <= tau) {
        int p = atomicAdd(&s_nact, 1);
        s_act[p] = tid;
    }
    __syncthreads();
    const int nact = s_nact;

    // scan active tiles, compact elements <= tau
    for (int a = 0; a < nact; a++) {
        int t = s_act[a];
        float v = d[t * 128 + tid];
        if (v <= tau) {
            int p = atomicAdd(&s_cnt, 1);
            if (p < BUFCAP) { bval[p] = v; bidx[p] = t * 128 + tid; }
        }
    }
    __syncthreads();
    const int m = (s_cnt < BUFCAP) ? s_cnt : BUFCAP;

    // rank-select: entry e's rank = #{f : (v_f, i_f) < (v_e, i_e)}
    for (int e = tid; e < m; e += 128) {
        float v = bval[e];
        int   j = bidx[e];
        int r = 0;
        for (int t = 0; t < m; t++) {
            float ov = bval[t];
            r += (ov < v) || (ov == v && bidx[t] < j);
        }
        if (r < KCAND) g_cand[row * KCAND + r] = j;
    }
}

// ---------------------------------------------------------------------------
// 3b) authoritative fp32 re-rank of the 16 candidates (reference arithmetic).
// ---------------------------------------------------------------------------
__global__ __launch_bounds__(128)
void refine_kernel(const float* __restrict__ x) {
    __shared__ float sxi[4][128];
    const int warp = threadIdx.x >> 5;
    const int lane = threadIdx.x & 31;
    const int row  = blockIdx.x * 4 + warp;

#pragma unroll
    for (int q = 0; q < 4; q++)
        sxi[warp][lane + 32 * q] = x[(size_t)row * C + lane + 32 * q];
    __syncwarp();

    float d = __int_as_float(0x7f800000);
    int   j = 0x7fffffff;
    if (lane < KCAND) {
        j = g_cand[row * KCAND + lane];
        const float* xj = x + (size_t)j * C;
        float acc = 0.f;
#pragma unroll
        for (int k = 0; k < C; k += 4) {
            float4 v = *reinterpret_cast<const float4*>(xj + k);
            acc = fmaf(sxi[warp][k + 0], v.x, acc);
            acc = fmaf(sxi[warp][k + 1], v.y, acc);
            acc = fmaf(sxi[warp][k + 2], v.z, acc);
            acc = fmaf(sxi[warp][k + 3], v.w, acc);
        }
        d = (g_sq[row] + g_sq[j]) - 2.f * acc;
    }

    float dv[KCAND];
    int   di[KCAND];
#pragma unroll
    for (int t = 0; t < KCAND; t++) {
        dv[t] = __shfl_sync(0xffffffffu, d, t);
        di[t] = __shfl_sync(0xffffffffu, j, t);
    }
    if (lane == 0) {
#pragma unroll
        for (int a = 0; a < KCAND - 1; a++)
#pragma unroll
            for (int bq = 0; bq < KCAND - 1; bq++) {
                bool sw = dv[bq] > dv[bq + 1] ||
                          (dv[bq] == dv[bq + 1] && di[bq] > di[bq + 1]);
                float tv = sw ? dv[bq + 1] : dv[bq];
                dv[bq + 1] = sw ? dv[bq] : dv[bq + 1]; dv[bq] = tv;
                int ti = sw ? di[bq + 1] : di[bq];
                di[bq + 1] = sw ? di[bq] : di[bq + 1]; di[bq] = ti;
            }
#pragma unroll
        for (int t = 0; t < KNN; t++) g_nbr[row * KNN + t] = di[t];
    }
}

// ---------------------------------------------------------------------------
// 4) x2 = x + rel_pos_table[rel]
// ---------------------------------------------------------------------------
__global__ void relpos_kernel(const float* __restrict__ x, const float* __restrict__ tab) {
    int idx = blockIdx.x * blockDim.x + threadIdx.x;
    int i   = idx >> 7;
    int c   = idx & 127;
    int rel = (i >> 7) - (i & 127) + (C - 1);
    g_x2[idx] = x[idx] + tab[(size_t)rel * C + c];
}

// ---------------------------------------------------------------------------
// 5) gather + max-relative + concat-GEMM (+ bias at the end). 16 rows/block.
// ---------------------------------------------------------------------------
__global__ __launch_bounds__(256)
void final_kernel(const float* __restrict__ W, const float* __restrict__ b,
                  float* __restrict__ out) {
    __shared__ float feat[16][260];
    const int r0   = blockIdx.x * 16;
    const int tid  = threadIdx.x;
    const int half = tid >> 7;
    const int c    = tid & 127;
    const float NEGINF = __int_as_float(0xff800000);

#pragma unroll
    for (int rr = 0; rr < 16; rr += 2) {
        int r = rr + half;
        int i = r0 + r;
        float xi = g_x2[(size_t)i * C + c];
        float m  = NEGINF;
#pragma unroll
        for (int k = 0; k < KNN; k++) {
            int j = g_nbr[i * KNN + k];
            m = fmaxf(m, g_x2[(size_t)j * C + c] - xi);
        }
        feat[r][c]     = xi;
        feat[r][C + c] = m;
    }
    __syncthreads();

    const int o = tid;
    float acc[16];
#pragma unroll
    for (int r = 0; r < 16; r++) acc[r] = 0.f;

    for (int f = 0; f < 2 * C; f += 4) {
        float w0 = W[(size_t)(f + 0) * COUT + o];
        float w1 = W[(size_t)(f + 1) * COUT + o];
        float w2 = W[(size_t)(f + 2) * COUT + o];
        float w3 = W[(size_t)(f + 3) * COUT + o];
#pragma unroll
        for (int r = 0; r < 16; r++) {
            float4 fv = *reinterpret_cast<const float4*>(&feat[r][f]);
            acc[r] = fmaf(fv.x, w0, acc[r]);
            acc[r] = fmaf(fv.y, w1, acc[r]);
            acc[r] = fmaf(fv.z, w2, acc[r]);
            acc[r] = fmaf(fv.w, w3, acc[r]);
        }
    }
    float bias = b[o];
#pragma unroll
    for (int r = 0; r < 16; r++)
        out[(size_t)(r0 + r) * COUT + o] = acc[r] + bias;
}

// ---------------------------------------------------------------------------
extern "C" void kernel_launch(void* const* d_in, const int* in_sizes, int n_in,
                              void* d_out, int out_size) {
    const float* x   = (const float*)d_in[0];
    const float* tab = (const float*)d_in[1];
    const float* W   = (const float*)d_in[2];
    const float* b   = (const float*)d_in[3];
    float* out = (float*)d_out;
    (void)in_sizes; (void)n_in; (void)out_size;

    const int smem_bytes = (4 * CHWORDS) * (int)sizeof(float) + 256 * (int)sizeof(unsigned);
    static bool attr_set = false;
    if (!attr_set) {
        cudaFuncSetAttribute(dist_kernel,
                             cudaFuncAttributeMaxDynamicSharedMemorySize, smem_bytes);
        attr_set = true;
    }

    sqnorm_kernel<<<(N + 255) / 256, 256>>>(x);
    dist_kernel<<<dim3(NTILE, NTILE), 256, smem_bytes>>>(x);
    topk_kernel<<<N, 128>>>();
    refine_kernel<<<N / 4, 128>>>(x);
    relpos_kernel<<<(N * C) / 256, 256>>>(x, tab);
    final_kernel<<<N / 16, 256>>>(W, b, out);
}

// round 13
// speedup vs baseline: 3.8849x; 1.1203x over previous
#include <cuda_runtime.h>
#include <cuda_fp16.h>
#include <cstdint>
#include <cstddef>

#define N      16384
#define C      128
#define KNN    9
#define KCAND  16
#define COUT   256
#define BUFCAP 1024
#define NTILE  (N / 128)       // 128 column tiles
#define SPITCH 36              // smem row pitch in words
#define CHWORDS (128 * SPITCH) // words per 128x32 chunk buffer
#define TPITCH 132             // transpose buffer pitch (words)

// Scratch (static __device__ arrays per harness rules; no cudaMalloc anywhere)
__device__ float    g_sq[N];
__device__ uint32_t g_xt[(size_t)N * C];       // x pre-rounded to tf32
__device__ __half   g_dist[(size_t)N * N];     // 512 MB half distance matrix
__device__ float    g_rowmin[N * NTILE];       // per (row, col tile) min (of stored halves)
__device__ int      g_cand[N * KCAND];
__device__ int      g_nbr[N * KNN];
__device__ float    g_x2[(size_t)N * C];

__device__ __forceinline__ uint32_t f2tf32(float f) {
    uint32_t u;
    asm("cvt.rna.tf32.f32 %0, %1;" : "=r"(u) : "f"(f));
    return u;
}
// monotone float->unsigned key (order-preserving for all finite floats + inf)
__device__ __forceinline__ unsigned fkey(float f) {
    unsigned u = __float_as_uint(f);
    return (u & 0x80000000u) ? ~u : (u | 0x80000000u);
}
__device__ __forceinline__ float funkey(unsigned k) {
    return __uint_as_float((k & 0x80000000u) ? (k & 0x7fffffffu) : ~k);
}
// round to the value that will be stored (half grid), back in fp32
__device__ __forceinline__ float hround(float f) {
    return __half2float(__float2half_rn(f));
}

// ---------------------------------------------------------------------------
// 1a) squared norms -- replicate an LLVM/XLA vectorized reduce.
// ---------------------------------------------------------------------------
__global__ void sqnorm_kernel(const float* __restrict__ x) {
    int i = blockIdx.x * blockDim.x + threadIdx.x;
    if (i >= N) return;
    const float* r = x + (size_t)i * C;
    float p[8];
#pragma unroll
    for (int l = 0; l < 8; l++) p[l] = 0.f;
#pragma unroll
    for (int k = 0; k < C / 8; k++)
#pragma unroll
        for (int l = 0; l < 8; l++) {
            float v = r[8 * k + l];
            p[l] = fmaf(v, v, p[l]);
        }
    float v0 = p[0] + p[4];
    float v1 = p[1] + p[5];
    float v2 = p[2] + p[6];
    float v3 = p[3] + p[7];
    g_sq[i] = (v0 + v2) + (v1 + v3);
}

// 1b) pre-round x to tf32 (removes cvt from the GEMM inner loop)
__global__ void xt_kernel(const float* __restrict__ x) {
    int idx = blockIdx.x * blockDim.x + threadIdx.x;
    g_xt[idx] = f2tf32(x[idx]);
}

// ---------------------------------------------------------------------------
// 2) SYMMETRIC monolithic distance GEMM (tf32 mma.sync, cp.async pipelined).
//    Upper-triangle tiles compute; off-diagonal tiles emit mirrored tile
//    (smem transpose) + per-column minima. dist stored as fp16; ALL minima
//    taken over the half-rounded values for selection consistency.
// ---------------------------------------------------------------------------
__device__ __forceinline__ void stage_chunk(int bi, int bj, int kc,
                                            uint32_t* As, uint32_t* Bs, int tid) {
#pragma unroll
    for (int v = 0; v < 4; v++) {
        int idx = tid + v * 256;         // 0..1023
        int row = idx >> 3;              // 0..127
        int c4  = (idx & 7) << 2;        // 0..28
        const uint32_t* ga = &g_xt[(size_t)(bi + row) * C + kc * 32 + c4];
        unsigned da = (unsigned)__cvta_generic_to_shared(&As[row * SPITCH + c4]);
        asm volatile("cp.async.cg.shared.global [%0], [%1], 16;" :: "r"(da), "l"(ga));
        const uint32_t* gb = &g_xt[(size_t)(bj + row) * C + kc * 32 + c4];
        unsigned db = (unsigned)__cvta_generic_to_shared(&Bs[row * SPITCH + c4]);
        asm volatile("cp.async.cg.shared.global [%0], [%1], 16;" :: "r"(db), "l"(gb));
    }
}

__global__ __launch_bounds__(256, 2)
void dist_kernel() {
    if (blockIdx.y > blockIdx.x) return;   // lower-triangle tiles mirrored

    extern __shared__ uint32_t smu[];
    uint32_t* Abuf[2] = { smu,            smu + 2 * CHWORDS };
    uint32_t* Bbuf[2] = { smu + CHWORDS,  smu + 3 * CHWORDS };
    unsigned* rmin = smu + 4 * CHWORDS;
    unsigned* cmin = rmin + 128;
    float*    smf  = (float*)smu;          // transpose buffer (reuse staging)

    const int tid  = threadIdx.x;
    const int warp = tid >> 5;
    const int lane = tid & 31;
    const int g    = lane >> 2;     // groupID
    const int tig  = lane & 3;      // thread-in-group
    const int wm   = warp & 3;      // warp row  (32 rows)
    const int wn   = warp >> 2;     // warp col  (64 cols)
    const int bi   = blockIdx.y * 128;
    const int bj   = blockIdx.x * 128;
    const bool mirror = (bi != bj);

    if (tid < 128) { rmin[tid] = 0xFFFFFFFFu; cmin[tid] = 0xFFFFFFFFu; }

    float acc[2][8][4];
#pragma unroll
    for (int mt = 0; mt < 2; mt++)
#pragma unroll
        for (int nt = 0; nt < 8; nt++)
#pragma unroll
            for (int e = 0; e < 4; e++) acc[mt][nt][e] = 0.f;

    stage_chunk(bi, bj, 0, Abuf[0], Bbuf[0], tid);
    asm volatile("cp.async.commit_group;");

#pragma unroll
    for (int kc = 0; kc < 4; kc++) {
        if (kc < 3) {
            stage_chunk(bi, bj, kc + 1, Abuf[(kc + 1) & 1], Bbuf[(kc + 1) & 1], tid);
            asm volatile("cp.async.commit_group;");
            asm volatile("cp.async.wait_group 1;");
        } else {
            asm volatile("cp.async.wait_group 0;");
        }
        __syncthreads();

        const uint32_t* As = Abuf[kc & 1];
        const uint32_t* Bs = Bbuf[kc & 1];
#pragma unroll
        for (int ks = 0; ks < 4; ks++) {
            const int k0 = ks * 8;
            uint32_t a[2][4];
#pragma unroll
            for (int mt = 0; mt < 2; mt++) {
                int rbase = (wm * 32 + mt * 16 + g) * SPITCH + k0 + tig;
                a[mt][0] = As[rbase];
                a[mt][1] = As[rbase + 8 * SPITCH];
                a[mt][2] = As[rbase + 4];
                a[mt][3] = As[rbase + 8 * SPITCH + 4];
            }
            uint32_t b[8][2];
#pragma unroll
            for (int nt = 0; nt < 8; nt++) {
                int cbase = (wn * 64 + nt * 8 + g) * SPITCH + k0 + tig;
                b[nt][0] = Bs[cbase];
                b[nt][1] = Bs[cbase + 4];
            }
#pragma unroll
            for (int mt = 0; mt < 2; mt++)
#pragma unroll
                for (int nt = 0; nt < 8; nt++)
                    asm volatile(
                        "mma.sync.aligned.m16n8k8.row.col.f32.tf32.tf32.f32 "
                        "{%0,%1,%2,%3}, {%4,%5,%6,%7}, {%8,%9}, {%0,%1,%2,%3};"
                        : "+f"(acc[mt][nt][0]), "+f"(acc[mt][nt][1]),
                          "+f"(acc[mt][nt][2]), "+f"(acc[mt][nt][3])
                        : "r"(a[mt][0]), "r"(a[mt][1]), "r"(a[mt][2]), "r"(a[mt][3]),
                          "r"(b[nt][0]), "r"(b[nt][1]));
        }
        __syncthreads();
    }
    // staging smem is free from here on (reused as transpose buffer)

    const float INFV = __int_as_float(0x7f800000);
    float cm[8][2];
#pragma unroll
    for (int nt = 0; nt < 8; nt++) { cm[nt][0] = INFV; cm[nt][1] = INFV; }

#pragma unroll
    for (int mt = 0; mt < 2; mt++) {
        int rl = wm * 32 + mt * 16 + g;        // local row (lo); hi = +8
        int r_lo = bi + rl, r_hi = r_lo + 8;
        float si_lo = g_sq[r_lo], si_hi = g_sq[r_hi];
        float mn_lo = INFV, mn_hi = INFV;
#pragma unroll
        for (int nt = 0; nt < 8; nt++) {
            int cl = wn * 64 + nt * 8 + 2 * tig;   // local col
            int c0 = bj + cl;
            float sj0 = g_sq[c0], sj1 = g_sq[c0 + 1];
            float d00 = (si_lo + sj0) - 2.f * acc[mt][nt][0];
            float d01 = (si_lo + sj1) - 2.f * acc[mt][nt][1];
            float d10 = (si_hi + sj0) - 2.f * acc[mt][nt][2];
            float d11 = (si_hi + sj1) - 2.f * acc[mt][nt][3];
            if (r_lo == c0)     d00 = INFV;
            if (r_lo == c0 + 1) d01 = INFV;
            if (r_hi == c0)     d10 = INFV;
            if (r_hi == c0 + 1) d11 = INFV;
            // round to the stored (half) grid -- all mins on stored values
            __half h00 = __float2half_rn(d00), h01 = __float2half_rn(d01);
            __half h10 = __float2half_rn(d10), h11 = __float2half_rn(d11);
            float f00 = __half2float(h00), f01 = __half2float(h01);
            float f10 = __half2float(h10), f11 = __half2float(h11);
            mn_lo = fminf(mn_lo, fminf(f00, f01));
            mn_hi = fminf(mn_hi, fminf(f10, f11));
            *reinterpret_cast<__half2*>(&g_dist[(size_t)r_lo * N + c0]) =
                __halves2half2(h00, h01);
            *reinterpret_cast<__half2*>(&g_dist[(size_t)r_hi * N + c0]) =
                __halves2half2(h10, h11);
            if (mirror) {
                cm[nt][0] = fminf(cm[nt][0], fminf(f00, f10));
                cm[nt][1] = fminf(cm[nt][1], fminf(f01, f11));
                smf[cl * TPITCH + rl]           = f00;
                smf[(cl + 1) * TPITCH + rl]     = f01;
                smf[cl * TPITCH + rl + 8]       = f10;
                smf[(cl + 1) * TPITCH + rl + 8] = f11;
            }
        }
        mn_lo = fminf(mn_lo, __shfl_xor_sync(0xffffffffu, mn_lo, 1));
        mn_lo = fminf(mn_lo, __shfl_xor_sync(0xffffffffu, mn_lo, 2));
        mn_hi = fminf(mn_hi, __shfl_xor_sync(0xffffffffu, mn_hi, 1));
        mn_hi = fminf(mn_hi, __shfl_xor_sync(0xffffffffu, mn_hi, 2));
        if (tig == 0) {
            atomicMin(&rmin[wm * 32 + mt * 16 + g],     fkey(mn_lo));
            atomicMin(&rmin[wm * 32 + mt * 16 + g + 8], fkey(mn_hi));
        }
    }

    if (mirror) {
#pragma unroll
        for (int nt = 0; nt < 8; nt++)
#pragma unroll
            for (int e = 0; e < 2; e++) {
                float v = cm[nt][e];
                v = fminf(v, __shfl_xor_sync(0xffffffffu, v, 4));
                v = fminf(v, __shfl_xor_sync(0xffffffffu, v, 8));
                v = fminf(v, __shfl_xor_sync(0xffffffffu, v, 16));
                if (lane < 4)
                    atomicMin(&cmin[wn * 64 + nt * 8 + 2 * tig + e], fkey(v));
            }
    }
    __syncthreads();

    if (tid < 128)
        g_rowmin[(bi + tid) * NTILE + blockIdx.x] = funkey(rmin[tid]);

    if (mirror) {
        // coalesced mirrored-tile store (half round-trip is bit-exact)
#pragma unroll
        for (int it = 0; it < 16; it++) {
            int idx = tid + it * 256;     // 0..4095
            int tr  = idx >> 5;           // 0..127
            int c4  = (idx & 31) << 2;    // 0..124
            float4 v = *reinterpret_cast<const float4*>(&smf[tr * TPITCH + c4]);
            __half2 h0 = __halves2half2(__float2half_rn(v.x), __float2half_rn(v.y));
            __half2 h1 = __halves2half2(__float2half_rn(v.z), __float2half_rn(v.w));
            *reinterpret_cast<__half2*>(&g_dist[(size_t)(bj + tr) * N + bi + c4])     = h0;
            *reinterpret_cast<__half2*>(&g_dist[(size_t)(bj + tr) * N + bi + c4 + 2]) = h1;
        }
        if (tid < 128)
            g_rowmin[(bj + tid) * NTILE + blockIdx.y] = funkey(cmin[tid]);
    }
}

// ---------------------------------------------------------------------------
// 3) per-row top-16 via hierarchical tile-min selection (exact by (val,idx)
//    over the stored half values).
// ---------------------------------------------------------------------------
__global__ __launch_bounds__(128)
void topk_kernel() {
    __shared__ float tmin[NTILE];
    __shared__ float s_tau;
    __shared__ int   s_act[NTILE];
    __shared__ int   s_nact;
    __shared__ int   s_cnt;
    __shared__ float bval[BUFCAP];
    __shared__ int   bidx[BUFCAP];

    const int row  = blockIdx.x;
    const __half* d = g_dist + (size_t)row * N;
    const int tid  = threadIdx.x;

    tmin[tid] = g_rowmin[row * NTILE + tid];
    if (tid == 0) { s_cnt = 0; s_nact = 0; }
    __syncthreads();

    // tau = tile-min with rank 15 under (val, tile) order
    float mv = tmin[tid];
    int rank = 0;
#pragma unroll 8
    for (int t = 0; t < NTILE; t++) {
        float ov = tmin[t];
        rank += (ov < mv) || (ov == mv && t < tid);
    }
    if (rank == 15) s_tau = mv;
    __syncthreads();
    const float tau = s_tau;

    // active tiles (min <= tau)
    if (tmin[tid] <= tau) {
        int p = atomicAdd(&s_nact, 1);
        s_act[p] = tid;
    }
    __syncthreads();
    const int nact = s_nact;

    // scan active tiles, compact elements <= tau
    for (int a = 0; a < nact; a++) {
        int t = s_act[a];
        float v = __half2float(d[t * 128 + tid]);
        if (v <= tau) {
            int p = atomicAdd(&s_cnt, 1);
            if (p < BUFCAP) { bval[p] = v; bidx[p] = t * 128 + tid; }
        }
    }
    __syncthreads();
    const int m = (s_cnt < BUFCAP) ? s_cnt : BUFCAP;

    // rank-select: entry e's rank = #{f : (v_f, i_f) < (v_e, i_e)}
    for (int e = tid; e < m; e += 128) {
        float v = bval[e];
        int   j = bidx[e];
        int r = 0;
        for (int t = 0; t < m; t++) {
            float ov = bval[t];
            r += (ov < v) || (ov == v && bidx[t] < j);
        }
        if (r < KCAND) g_cand[row * KCAND + r] = j;
    }
}

// ---------------------------------------------------------------------------
// 3b) authoritative fp32 re-rank of the 16 candidates (reference arithmetic).
// ---------------------------------------------------------------------------
__global__ __launch_bounds__(128)
void refine_kernel(const float* __restrict__ x) {
    __shared__ float sxi[4][128];
    const int warp = threadIdx.x >> 5;
    const int lane = threadIdx.x & 31;
    const int row  = blockIdx.x * 4 + warp;

#pragma unroll
    for (int q = 0; q < 4; q++)
        sxi[warp][lane + 32 * q] = x[(size_t)row * C + lane + 32 * q];
    __syncwarp();

    float d = __int_as_float(0x7f800000);
    int   j = 0x7fffffff;
    if (lane < KCAND) {
        j = g_cand[row * KCAND + lane];
        const float* xj = x + (size_t)j * C;
        float acc = 0.f;
#pragma unroll
        for (int k = 0; k < C; k += 4) {
            float4 v = *reinterpret_cast<const float4*>(xj + k);
            acc = fmaf(sxi[warp][k + 0], v.x, acc);
            acc = fmaf(sxi[warp][k + 1], v.y, acc);
            acc = fmaf(sxi[warp][k + 2], v.z, acc);
            acc = fmaf(sxi[warp][k + 3], v.w, acc);
        }
        d = (g_sq[row] + g_sq[j]) - 2.f * acc;
    }

    float dv[KCAND];
    int   di[KCAND];
#pragma unroll
    for (int t = 0; t < KCAND; t++) {
        dv[t] = __shfl_sync(0xffffffffu, d, t);
        di[t] = __shfl_sync(0xffffffffu, j, t);
    }
    if (lane == 0) {
#pragma unroll
        for (int a = 0; a < KCAND - 1; a++)
#pragma unroll
            for (int bq = 0; bq < KCAND - 1; bq++) {
                bool sw = dv[bq] > dv[bq + 1] ||
                          (dv[bq] == dv[bq + 1] && di[bq] > di[bq + 1]);
                float tv = sw ? dv[bq + 1] : dv[bq];
                dv[bq + 1] = sw ? dv[bq] : dv[bq + 1]; dv[bq] = tv;
                int ti = sw ? di[bq + 1] : di[bq];
                di[bq + 1] = sw ? di[bq] : di[bq + 1]; di[bq] = ti;
            }
#pragma unroll
        for (int t = 0; t < KNN; t++) g_nbr[row * KNN + t] = di[t];
    }
}

// ---------------------------------------------------------------------------
// 4) x2 = x + rel_pos_table[rel]
// ---------------------------------------------------------------------------
__global__ void relpos_kernel(const float* __restrict__ x, const float* __restrict__ tab) {
    int idx = blockIdx.x * blockDim.x + threadIdx.x;
    int i   = idx >> 7;
    int c   = idx & 127;
    int rel = (i >> 7) - (i & 127) + (C - 1);
    g_x2[idx] = x[idx] + tab[(size_t)rel * C + c];
}

// ---------------------------------------------------------------------------
// 5) gather + max-relative + concat-GEMM (+ bias at the end). 16 rows/block.
// ---------------------------------------------------------------------------
__global__ __launch_bounds__(256)
void final_kernel(const float* __restrict__ W, const float* __restrict__ b,
                  float* __restrict__ out) {
    __shared__ float feat[16][260];
    const int r0   = blockIdx.x * 16;
    const int tid  = threadIdx.x;
    const int half = tid >> 7;
    const int c    = tid & 127;
    const float NEGINF = __int_as_float(0xff800000);

#pragma unroll
    for (int rr = 0; rr < 16; rr += 2) {
        int r = rr + half;
        int i = r0 + r;
        float xi = g_x2[(size_t)i * C + c];
        float m  = NEGINF;
#pragma unroll
        for (int k = 0; k < KNN; k++) {
            int j = g_nbr[i * KNN + k];
            m = fmaxf(m, g_x2[(size_t)j * C + c] - xi);
        }
        feat[r][c]     = xi;
        feat[r][C + c] = m;
    }
    __syncthreads();

    const int o = tid;
    float acc[16];
#pragma unroll
    for (int r = 0; r < 16; r++) acc[r] = 0.f;

    for (int f = 0; f < 2 * C; f += 4) {
        float w0 = W[(size_t)(f + 0) * COUT + o];
        float w1 = W[(size_t)(f + 1) * COUT + o];
        float w2 = W[(size_t)(f + 2) * COUT + o];
        float w3 = W[(size_t)(f + 3) * COUT + o];
#pragma unroll
        for (int r = 0; r < 16; r++) {
            float4 fv = *reinterpret_cast<const float4*>(&feat[r][f]);
            acc[r] = fmaf(fv.x, w0, acc[r]);
            acc[r] = fmaf(fv.y, w1, acc[r]);
            acc[r] = fmaf(fv.z, w2, acc[r]);
            acc[r] = fmaf(fv.w, w3, acc[r]);
        }
    }
    float bias = b[o];
#pragma unroll
    for (int r = 0; r < 16; r++)
        out[(size_t)(r0 + r) * COUT + o] = acc[r] + bias;
}

// ---------------------------------------------------------------------------
extern "C" void kernel_launch(void* const* d_in, const int* in_sizes, int n_in,
                              void* d_out, int out_size) {
    const float* x   = (const float*)d_in[0];
    const float* tab = (const float*)d_in[1];
    const float* W   = (const float*)d_in[2];
    const float* b   = (const float*)d_in[3];
    float* out = (float*)d_out;
    (void)in_sizes; (void)n_in; (void)out_size;

    const int smem_bytes = (4 * CHWORDS) * (int)sizeof(uint32_t) + 256 * (int)sizeof(unsigned);
    static bool attr_set = false;
    if (!attr_set) {
        cudaFuncSetAttribute(dist_kernel,
                             cudaFuncAttributeMaxDynamicSharedMemorySize, smem_bytes);
        attr_set = true;
    }

    sqnorm_kernel<<<(N + 255) / 256, 256>>>(x);
    xt_kernel<<<(N * C) / 256, 256>>>(x);
    dist_kernel<<<dim3(NTILE, NTILE), 256, smem_bytes>>>();
    topk_kernel<<<N, 128>>>();
    refine_kernel<<<N / 4, 128>>>(x);
    relpos_kernel<<<(N * C) / 256, 256>>>(x, tab);
    final_kernel<<<N / 16, 256>>>(W, b, out);
}

// round 14
// speedup vs baseline: 3.8892x; 1.0011x over previous
#include <cuda_runtime.h>
#include <cuda_fp16.h>
#include <cstdint>
#include <cstddef>

#define N      16384
#define C      128
#define KNN    9
#define KCAND  20
#define COUT   256
#define BUFCAP 1024
#define NTILE  (N / 128)       // 128 column tiles
#define SPITCH 36              // smem row pitch in 32-bit words (32 data + 4 pad)
#define CHWORDS (128 * SPITCH) // words per 128x(64 bf16) chunk buffer
#define TPITCH 132             // transpose buffer pitch (words)

// Scratch (static __device__ arrays per harness rules; no cudaMalloc anywhere)
__device__ float    g_sq[N];
__device__ uint32_t g_xb[(size_t)N * (C / 2)];  // x as packed bf16x2 (4 MB)
__device__ __half   g_dist[(size_t)N * N];      // 512 MB half distance matrix
__device__ float    g_rowmin[N * NTILE];        // per (row, col tile) min of stored halves
__device__ int      g_cand[N * KCAND];
__device__ int      g_nbr[N * KNN];
__device__ float    g_x2[(size_t)N * C];

// monotone float->unsigned key (order-preserving)
__device__ __forceinline__ unsigned fkey(float f) {
    unsigned u = __float_as_uint(f);
    return (u & 0x80000000u) ? ~u : (u | 0x80000000u);
}
__device__ __forceinline__ float funkey(unsigned k) {
    return __uint_as_float((k & 0x80000000u) ? (k & 0x7fffffffu) : ~k);
}

// ---------------------------------------------------------------------------
// 1a) squared norms -- replicate an LLVM/XLA vectorized reduce.
// ---------------------------------------------------------------------------
__global__ void sqnorm_kernel(const float* __restrict__ x) {
    int i = blockIdx.x * blockDim.x + threadIdx.x;
    if (i >= N) return;
    const float* r = x + (size_t)i * C;
    float p[8];
#pragma unroll
    for (int l = 0; l < 8; l++) p[l] = 0.f;
#pragma unroll
    for (int k = 0; k < C / 8; k++)
#pragma unroll
        for (int l = 0; l < 8; l++) {
            float v = r[8 * k + l];
            p[l] = fmaf(v, v, p[l]);
        }
    float v0 = p[0] + p[4];
    float v1 = p[1] + p[5];
    float v2 = p[2] + p[6];
    float v3 = p[3] + p[7];
    g_sq[i] = (v0 + v2) + (v1 + v3);
}

// 1b) pack x to bf16x2 (element 2k in low half, 2k+1 in high half)
__global__ void xb_kernel(const float* __restrict__ x) {
    int idx = blockIdx.x * blockDim.x + threadIdx.x;   // over N*C/2
    float2 v = reinterpret_cast<const float2*>(x)[idx];
    uint32_t p;
    asm("cvt.rn.bf16x2.f32 %0, %1, %2;" : "=r"(p) : "f"(v.y), "f"(v.x));
    g_xb[idx] = p;
}

// ---------------------------------------------------------------------------
// 2) SYMMETRIC monolithic distance GEMM, bf16 mma.sync m16n8k16, cp.async
//    double-buffered (2 chunks of K=64). Nomination only -- fp32-exact refine
//    is the ranking authority. dist stored fp16; all minima over stored halves.
// ---------------------------------------------------------------------------
__device__ __forceinline__ void stage_chunk(int bi, int bj, int kc,
                                            uint32_t* As, uint32_t* Bs, int tid) {
#pragma unroll
    for (int v = 0; v < 4; v++) {
        int idx = tid + v * 256;         // 0..1023
        int row = idx >> 3;              // 0..127
        int c4  = (idx & 7) << 2;        // 0..28  (words)
        const uint32_t* ga = &g_xb[(size_t)(bi + row) * (C / 2) + kc * 32 + c4];
        unsigned da = (unsigned)__cvta_generic_to_shared(&As[row * SPITCH + c4]);
        asm volatile("cp.async.cg.shared.global [%0], [%1], 16;" :: "r"(da), "l"(ga));
        const uint32_t* gb = &g_xb[(size_t)(bj + row) * (C / 2) + kc * 32 + c4];
        unsigned db = (unsigned)__cvta_generic_to_shared(&Bs[row * SPITCH + c4]);
        asm volatile("cp.async.cg.shared.global [%0], [%1], 16;" :: "r"(db), "l"(gb));
    }
}

__global__ __launch_bounds__(256, 2)
void dist_kernel() {
    if (blockIdx.y > blockIdx.x) return;   // lower-triangle tiles mirrored

    extern __shared__ uint32_t smu[];
    uint32_t* Abuf[2] = { smu,            smu + 2 * CHWORDS };
    uint32_t* Bbuf[2] = { smu + CHWORDS,  smu + 3 * CHWORDS };
    unsigned* rmin = smu + 4 * CHWORDS;
    unsigned* cmin = rmin + 128;
    float*    smf  = (float*)smu;          // transpose buffer (reuse staging)

    const int tid  = threadIdx.x;
    const int warp = tid >> 5;
    const int lane = tid & 31;
    const int g    = lane >> 2;     // groupID
    const int tig  = lane & 3;      // thread-in-group
    const int wm   = warp & 3;      // warp row  (32 rows)
    const int wn   = warp >> 2;     // warp col  (64 cols)
    const int bi   = blockIdx.y * 128;
    const int bj   = blockIdx.x * 128;
    const bool mirror = (bi != bj);

    if (tid < 128) { rmin[tid] = 0xFFFFFFFFu; cmin[tid] = 0xFFFFFFFFu; }

    float acc[2][8][4];
#pragma unroll
    for (int mt = 0; mt < 2; mt++)
#pragma unroll
        for (int nt = 0; nt < 8; nt++)
#pragma unroll
            for (int e = 0; e < 4; e++) acc[mt][nt][e] = 0.f;

    stage_chunk(bi, bj, 0, Abuf[0], Bbuf[0], tid);
    asm volatile("cp.async.commit_group;");

#pragma unroll
    for (int kc = 0; kc < 2; kc++) {
        if (kc < 1) {
            stage_chunk(bi, bj, 1, Abuf[1], Bbuf[1], tid);
            asm volatile("cp.async.commit_group;");
            asm volatile("cp.async.wait_group 1;");
        } else {
            asm volatile("cp.async.wait_group 0;");
        }
        __syncthreads();

        const uint32_t* As = Abuf[kc];
        const uint32_t* Bs = Bbuf[kc];
#pragma unroll
        for (int ks = 0; ks < 4; ks++) {
            const int k0 = ks * 8;       // 8 words = 16 bf16 elements
            uint32_t a[2][4];
#pragma unroll
            for (int mt = 0; mt < 2; mt++) {
                int rbase = (wm * 32 + mt * 16 + g) * SPITCH + k0 + tig;
                a[mt][0] = As[rbase];                    // (g,   2tig..+1)
                a[mt][1] = As[rbase + 8 * SPITCH];       // (g+8, 2tig..+1)
                a[mt][2] = As[rbase + 4];                // (g,   2tig+8..+9)
                a[mt][3] = As[rbase + 8 * SPITCH + 4];   // (g+8, 2tig+8..+9)
            }
            uint32_t b[8][2];
#pragma unroll
            for (int nt = 0; nt < 8; nt++) {
                int cbase = (wn * 64 + nt * 8 + g) * SPITCH + k0 + tig;
                b[nt][0] = Bs[cbase];
                b[nt][1] = Bs[cbase + 4];
            }
#pragma unroll
            for (int mt = 0; mt < 2; mt++)
#pragma unroll
                for (int nt = 0; nt < 8; nt++)
                    asm volatile(
                        "mma.sync.aligned.m16n8k16.row.col.f32.bf16.bf16.f32 "
                        "{%0,%1,%2,%3}, {%4,%5,%6,%7}, {%8,%9}, {%0,%1,%2,%3};"
                        : "+f"(acc[mt][nt][0]), "+f"(acc[mt][nt][1]),
                          "+f"(acc[mt][nt][2]), "+f"(acc[mt][nt][3])
                        : "r"(a[mt][0]), "r"(a[mt][1]), "r"(a[mt][2]), "r"(a[mt][3]),
                          "r"(b[nt][0]), "r"(b[nt][1]));
        }
        __syncthreads();
    }
    // staging smem is free from here on (reused as transpose buffer)

    const float INFV = __int_as_float(0x7f800000);
    float cm[8][2];
#pragma unroll
    for (int nt = 0; nt < 8; nt++) { cm[nt][0] = INFV; cm[nt][1] = INFV; }

#pragma unroll
    for (int mt = 0; mt < 2; mt++) {
        int rl = wm * 32 + mt * 16 + g;        // local row (lo); hi = +8
        int r_lo = bi + rl, r_hi = r_lo + 8;
        float si_lo = g_sq[r_lo], si_hi = g_sq[r_hi];
        float mn_lo = INFV, mn_hi = INFV;
#pragma unroll
        for (int nt = 0; nt < 8; nt++) {
            int cl = wn * 64 + nt * 8 + 2 * tig;   // local col
            int c0 = bj + cl;
            float sj0 = g_sq[c0], sj1 = g_sq[c0 + 1];
            float d00 = (si_lo + sj0) - 2.f * acc[mt][nt][0];
            float d01 = (si_lo + sj1) - 2.f * acc[mt][nt][1];
            float d10 = (si_hi + sj0) - 2.f * acc[mt][nt][2];
            float d11 = (si_hi + sj1) - 2.f * acc[mt][nt][3];
            if (r_lo == c0)     d00 = INFV;
            if (r_lo == c0 + 1) d01 = INFV;
            if (r_hi == c0)     d10 = INFV;
            if (r_hi == c0 + 1) d11 = INFV;
            __half h00 = __float2half_rn(d00), h01 = __float2half_rn(d01);
            __half h10 = __float2half_rn(d10), h11 = __float2half_rn(d11);
            float f00 = __half2float(h00), f01 = __half2float(h01);
            float f10 = __half2float(h10), f11 = __half2float(h11);
            mn_lo = fminf(mn_lo, fminf(f00, f01));
            mn_hi = fminf(mn_hi, fminf(f10, f11));
            *reinterpret_cast<__half2*>(&g_dist[(size_t)r_lo * N + c0]) =
                __halves2half2(h00, h01);
            *reinterpret_cast<__half2*>(&g_dist[(size_t)r_hi * N + c0]) =
                __halves2half2(h10, h11);
            if (mirror) {
                cm[nt][0] = fminf(cm[nt][0], fminf(f00, f10));
                cm[nt][1] = fminf(cm[nt][1], fminf(f01, f11));
                smf[cl * TPITCH + rl]           = f00;
                smf[(cl + 1) * TPITCH + rl]     = f01;
                smf[cl * TPITCH + rl + 8]       = f10;
                smf[(cl + 1) * TPITCH + rl + 8] = f11;
            }
        }
        mn_lo = fminf(mn_lo, __shfl_xor_sync(0xffffffffu, mn_lo, 1));
        mn_lo = fminf(mn_lo, __shfl_xor_sync(0xffffffffu, mn_lo, 2));
        mn_hi = fminf(mn_hi, __shfl_xor_sync(0xffffffffu, mn_hi, 1));
        mn_hi = fminf(mn_hi, __shfl_xor_sync(0xffffffffu, mn_hi, 2));
        if (tig == 0) {
            atomicMin(&rmin[wm * 32 + mt * 16 + g],     fkey(mn_lo));
            atomicMin(&rmin[wm * 32 + mt * 16 + g + 8], fkey(mn_hi));
        }
    }

    if (mirror) {
#pragma unroll
        for (int nt = 0; nt < 8; nt++)
#pragma unroll
            for (int e = 0; e < 2; e++) {
                float v = cm[nt][e];
                v = fminf(v, __shfl_xor_sync(0xffffffffu, v, 4));
                v = fminf(v, __shfl_xor_sync(0xffffffffu, v, 8));
                v = fminf(v, __shfl_xor_sync(0xffffffffu, v, 16));
                if (lane < 4)
                    atomicMin(&cmin[wn * 64 + nt * 8 + 2 * tig + e], fkey(v));
            }
    }
    __syncthreads();

    if (tid < 128)
        g_rowmin[(bi + tid) * NTILE + blockIdx.x] = funkey(rmin[tid]);

    if (mirror) {
        // coalesced mirrored-tile store (half round-trip is bit-exact)
#pragma unroll
        for (int it = 0; it < 16; it++) {
            int idx = tid + it * 256;     // 0..4095
            int tr  = idx >> 5;           // 0..127
            int c4  = (idx & 31) << 2;    // 0..124
            float4 v = *reinterpret_cast<const float4*>(&smf[tr * TPITCH + c4]);
            __half2 h0 = __halves2half2(__float2half_rn(v.x), __float2half_rn(v.y));
            __half2 h1 = __halves2half2(__float2half_rn(v.z), __float2half_rn(v.w));
            *reinterpret_cast<__half2*>(&g_dist[(size_t)(bj + tr) * N + bi + c4])     = h0;
            *reinterpret_cast<__half2*>(&g_dist[(size_t)(bj + tr) * N + bi + c4 + 2]) = h1;
        }
        if (tid < 128)
            g_rowmin[(bj + tid) * NTILE + blockIdx.y] = funkey(cmin[tid]);
    }
}

// ---------------------------------------------------------------------------
// 3) per-row top-20 via hierarchical tile-min selection.
//    tau = 20th smallest of 32 group-of-4 minima (each group-min is a
//    distinct element => >=20 elements <= tau). Scan tiles with min <= tau,
//    compact, rank-select by (val, idx) over stored half values.
// ---------------------------------------------------------------------------
__global__ __launch_bounds__(128)
void topk_kernel() {
    __shared__ float tmin[NTILE];
    __shared__ float gmin[32];
    __shared__ float s_tau;
    __shared__ int   s_act[NTILE];
    __shared__ int   s_nact;
    __shared__ int   s_cnt;
    __shared__ float bval[BUFCAP];
    __shared__ int   bidx[BUFCAP];

    const int row  = blockIdx.x;
    const __half* d = g_dist + (size_t)row * N;
    const int tid  = threadIdx.x;

    tmin[tid] = g_rowmin[row * NTILE + tid];
    if (tid == 0) { s_cnt = 0; s_nact = 0; }
    __syncthreads();

    if (tid < 32) {
        float a0 = tmin[4 * tid], a1 = tmin[4 * tid + 1];
        float a2 = tmin[4 * tid + 2], a3 = tmin[4 * tid + 3];
        gmin[tid] = fminf(fminf(a0, a1), fminf(a2, a3));
    }
    __syncthreads();

    if (tid < 32) {
        float v = gmin[tid];
        int rank = 0;
#pragma unroll
        for (int t = 0; t < 32; t++) {
            float ov = gmin[t];
            rank += (ov < v) || (ov == v && t < tid);
        }
        if (rank == KCAND - 1) s_tau = v;
    }
    __syncthreads();
    const float tau = s_tau;

    // active tiles (min <= tau)
    if (tmin[tid] <= tau) {
        int p = atomicAdd(&s_nact, 1);
        s_act[p] = tid;
    }
    __syncthreads();
    const int nact = s_nact;

    // scan active tiles, compact elements <= tau
    for (int a = 0; a < nact; a++) {
        int t = s_act[a];
        float v = __half2float(d[t * 128 + tid]);
        if (v <= tau) {
            int p = atomicAdd(&s_cnt, 1);
            if (p < BUFCAP) { bval[p] = v; bidx[p] = t * 128 + tid; }
        }
    }
    __syncthreads();
    const int m = (s_cnt < BUFCAP) ? s_cnt : BUFCAP;

    // rank-select: entry e's rank = #{f : (v_f, i_f) < (v_e, i_e)}
    for (int e = tid; e < m; e += 128) {
        float v = bval[e];
        int   j = bidx[e];
        int r = 0;
        for (int t = 0; t < m; t++) {
            float ov = bval[t];
            r += (ov < v) || (ov == v && bidx[t] < j);
        }
        if (r < KCAND) g_cand[row * KCAND + r] = j;
    }
}

// ---------------------------------------------------------------------------
// 3b) authoritative fp32 re-rank of the 20 candidates (reference arithmetic).
//     One warp per row; lane t owns candidate t.
// ---------------------------------------------------------------------------
__global__ __launch_bounds__(128)
void refine_kernel(const float* __restrict__ x) {
    __shared__ float sxi[4][128];
    const int warp = threadIdx.x >> 5;
    const int lane = threadIdx.x & 31;
    const int row  = blockIdx.x * 4 + warp;

#pragma unroll
    for (int q = 0; q < 4; q++)
        sxi[warp][lane + 32 * q] = x[(size_t)row * C + lane + 32 * q];
    __syncwarp();

    float d = __int_as_float(0x7f800000);
    int   j = 0x7fffffff;
    if (lane < KCAND) {
        j = g_cand[row * KCAND + lane];
        const float* xj = x + (size_t)j * C;
        float acc = 0.f;
#pragma unroll
        for (int k = 0; k < C; k += 4) {
            float4 v = *reinterpret_cast<const float4*>(xj + k);
            acc = fmaf(sxi[warp][k + 0], v.x, acc);
            acc = fmaf(sxi[warp][k + 1], v.y, acc);
            acc = fmaf(sxi[warp][k + 2], v.z, acc);
            acc = fmaf(sxi[warp][k + 3], v.w, acc);
        }
        d = (g_sq[row] + g_sq[j]) - 2.f * acc;
    }

    float dv[KCAND];
    int   di[KCAND];
#pragma unroll
    for (int t = 0; t < KCAND; t++) {
        dv[t] = __shfl_sync(0xffffffffu, d, t);
        di[t] = __shfl_sync(0xffffffffu, j, t);
    }
    if (lane == 0) {
#pragma unroll
        for (int a = 0; a < KCAND - 1; a++)
#pragma unroll
            for (int bq = 0; bq < KCAND - 1; bq++) {
                bool sw = dv[bq] > dv[bq + 1] ||
                          (dv[bq] == dv[bq + 1] && di[bq] > di[bq + 1]);
                float tv = sw ? dv[bq + 1] : dv[bq];
                dv[bq + 1] = sw ? dv[bq] : dv[bq + 1]; dv[bq] = tv;
                int ti = sw ? di[bq + 1] : di[bq];
                di[bq + 1] = sw ? di[bq] : di[bq + 1]; di[bq] = ti;
            }
#pragma unroll
        for (int t = 0; t < KNN; t++) g_nbr[row * KNN + t] = di[t];
    }
}

// ---------------------------------------------------------------------------
// 4) x2 = x + rel_pos_table[rel]
// ---------------------------------------------------------------------------
__global__ void relpos_kernel(const float* __restrict__ x, const float* __restrict__ tab) {
    int idx = blockIdx.x * blockDim.x + threadIdx.x;
    int i   = idx >> 7;
    int c   = idx & 127;
    int rel = (i >> 7) - (i & 127) + (C - 1);
    g_x2[idx] = x[idx] + tab[(size_t)rel * C + c];
}

// ---------------------------------------------------------------------------
// 5) gather + max-relative + concat-GEMM (+ bias at the end). 16 rows/block.
// ---------------------------------------------------------------------------
__global__ __launch_bounds__(256)
void final_kernel(const float* __restrict__ W, const float* __restrict__ b,
                  float* __restrict__ out) {
    __shared__ float feat[16][260];
    const int r0   = blockIdx.x * 16;
    const int tid  = threadIdx.x;
    const int half = tid >> 7;
    const int c    = tid & 127;
    const float NEGINF = __int_as_float(0xff800000);

#pragma unroll
    for (int rr = 0; rr < 16; rr += 2) {
        int r = rr + half;
        int i = r0 + r;
        float xi = g_x2[(size_t)i * C + c];
        float m  = NEGINF;
#pragma unroll
        for (int k = 0; k < KNN; k++) {
            int j = g_nbr[i * KNN + k];
            m = fmaxf(m, g_x2[(size_t)j * C + c] - xi);
        }
        feat[r][c]     = xi;
        feat[r][C + c] = m;
    }
    __syncthreads();

    const int o = tid;
    float acc[16];
#pragma unroll
    for (int r = 0; r < 16; r++) acc[r] = 0.f;

    for (int f = 0; f < 2 * C; f += 4) {
        float w0 = W[(size_t)(f + 0) * COUT + o];
        float w1 = W[(size_t)(f + 1) * COUT + o];
        float w2 = W[(size_t)(f + 2) * COUT + o];
        float w3 = W[(size_t)(f + 3) * COUT + o];
#pragma unroll
        for (int r = 0; r < 16; r++) {
            float4 fv = *reinterpret_cast<const float4*>(&feat[r][f]);
            acc[r] = fmaf(fv.x, w0, acc[r]);
            acc[r] = fmaf(fv.y, w1, acc[r]);
            acc[r] = fmaf(fv.z, w2, acc[r]);
            acc[r] = fmaf(fv.w, w3, acc[r]);
        }
    }
    float bias = b[o];
#pragma unroll
    for (int r = 0; r < 16; r++)
        out[(size_t)(r0 + r) * COUT + o] = acc[r] + bias;
}

// ---------------------------------------------------------------------------
extern "C" void kernel_launch(void* const* d_in, const int* in_sizes, int n_in,
                              void* d_out, int out_size) {
    const float* x   = (const float*)d_in[0];
    const float* tab = (const float*)d_in[1];
    const float* W   = (const float*)d_in[2];
    const float* b   = (const float*)d_in[3];
    float* out = (float*)d_out;
    (void)in_sizes; (void)n_in; (void)out_size;

    const int smem_bytes = (4 * CHWORDS) * (int)sizeof(uint32_t) + 256 * (int)sizeof(unsigned);
    static bool attr_set = false;
    if (!attr_set) {
        cudaFuncSetAttribute(dist_kernel,
                             cudaFuncAttributeMaxDynamicSharedMemorySize, smem_bytes);
        attr_set = true;
    }

    sqnorm_kernel<<<(N + 255) / 256, 256>>>(x);
    xb_kernel<<<(N * C / 2) / 256, 256>>>(x);
    dist_kernel<<<dim3(NTILE, NTILE), 256, smem_bytes>>>();
    topk_kernel<<<N, 128>>>();
    refine_kernel<<<N / 4, 128>>>(x);
    relpos_kernel<<<(N * C) / 256, 256>>>(x, tab);
    final_kernel<<<N / 16, 256>>>(W, b, out);
}

// round 15
// speedup vs baseline: 4.0372x; 1.0381x over previous
#include <cuda_runtime.h>
#include <cuda_fp16.h>
#include <cstdint>
#include <cstddef>

#define N      16384
#define C      128
#define KNN    9
#define KCAND  20
#define COUT   256
#define BUFCAP 1024
#define NTILE  (N / 128)       // 128 column tiles
#define SPITCH 36              // smem row pitch in 32-bit words (32 data + 4 pad)
#define CHWORDS (128 * SPITCH) // words per 128x(64 bf16) chunk buffer
#define TPITCH 132             // transpose buffer pitch (words)

// Scratch (static __device__ arrays per harness rules; no cudaMalloc anywhere)
__device__ float    g_sq[N];
__device__ uint32_t g_xb[(size_t)N * (C / 2)];  // x as packed bf16x2 (4 MB)
__device__ __half   g_dist[(size_t)N * N];      // 512 MB half distance matrix
__device__ float    g_rowmin[N * NTILE];        // per (row, col tile) min of stored halves
__device__ int      g_cand[N * KCAND];
__device__ int      g_nbr[N * KNN];
__device__ float    g_x2[(size_t)N * C];

// monotone float->unsigned key (order-preserving)
__device__ __forceinline__ unsigned fkey(float f) {
    unsigned u = __float_as_uint(f);
    return (u & 0x80000000u) ? ~u : (u | 0x80000000u);
}
__device__ __forceinline__ float funkey(unsigned k) {
    return __uint_as_float((k & 0x80000000u) ? (k & 0x7fffffffu) : ~k);
}

// ---------------------------------------------------------------------------
// 1) fused: squared norms (LLVM/XLA vectorized-reduce order) + bf16x2 pack.
// ---------------------------------------------------------------------------
__global__ void prep_kernel(const float* __restrict__ x) {
    int i = blockIdx.x * blockDim.x + threadIdx.x;
    if (i >= N) return;
    const float* r = x + (size_t)i * C;
    uint32_t* pb = g_xb + (size_t)i * (C / 2);
    float p[8];
#pragma unroll
    for (int l = 0; l < 8; l++) p[l] = 0.f;
#pragma unroll
    for (int k = 0; k < C / 8; k++) {
        float v[8];
#pragma unroll
        for (int l = 0; l < 8; l++) {
            v[l] = r[8 * k + l];
            p[l] = fmaf(v[l], v[l], p[l]);
        }
#pragma unroll
        for (int q = 0; q < 4; q++) {
            uint32_t pk;
            asm("cvt.rn.bf16x2.f32 %0, %1, %2;" : "=r"(pk)
                : "f"(v[2 * q + 1]), "f"(v[2 * q]));
            pb[4 * k + q] = pk;
        }
    }
    float v0 = p[0] + p[4];
    float v1 = p[1] + p[5];
    float v2 = p[2] + p[6];
    float v3 = p[3] + p[7];
    g_sq[i] = (v0 + v2) + (v1 + v3);
}

// ---------------------------------------------------------------------------
// 2) SYMMETRIC monolithic distance GEMM, bf16 mma.sync m16n8k16, cp.async
//    double-buffered (2 chunks of K=64). Nomination only -- fp32-exact refine
//    is the ranking authority. dist stored fp16; all minima over stored halves.
// ---------------------------------------------------------------------------
__device__ __forceinline__ void stage_chunk(int bi, int bj, int kc,
                                            uint32_t* As, uint32_t* Bs, int tid) {
#pragma unroll
    for (int v = 0; v < 4; v++) {
        int idx = tid + v * 256;         // 0..1023
        int row = idx >> 3;              // 0..127
        int c4  = (idx & 7) << 2;        // 0..28  (words)
        const uint32_t* ga = &g_xb[(size_t)(bi + row) * (C / 2) + kc * 32 + c4];
        unsigned da = (unsigned)__cvta_generic_to_shared(&As[row * SPITCH + c4]);
        asm volatile("cp.async.cg.shared.global [%0], [%1], 16;" :: "r"(da), "l"(ga));
        const uint32_t* gb = &g_xb[(size_t)(bj + row) * (C / 2) + kc * 32 + c4];
        unsigned db = (unsigned)__cvta_generic_to_shared(&Bs[row * SPITCH + c4]);
        asm volatile("cp.async.cg.shared.global [%0], [%1], 16;" :: "r"(db), "l"(gb));
    }
}

__global__ __launch_bounds__(256, 2)
void dist_kernel() {
    if (blockIdx.y > blockIdx.x) return;   // lower-triangle tiles mirrored

    extern __shared__ uint32_t smu[];
    uint32_t* Abuf[2] = { smu,            smu + 2 * CHWORDS };
    uint32_t* Bbuf[2] = { smu + CHWORDS,  smu + 3 * CHWORDS };
    unsigned* rmin = smu + 4 * CHWORDS;
    unsigned* cmin = rmin + 128;
    float*    smf  = (float*)smu;          // transpose buffer (reuse staging)

    const int tid  = threadIdx.x;
    const int warp = tid >> 5;
    const int lane = tid & 31;
    const int g    = lane >> 2;     // groupID
    const int tig  = lane & 3;      // thread-in-group
    const int wm   = warp & 3;      // warp row  (32 rows)
    const int wn   = warp >> 2;     // warp col  (64 cols)
    const int bi   = blockIdx.y * 128;
    const int bj   = blockIdx.x * 128;
    const bool mirror = (bi != bj);

    if (tid < 128) { rmin[tid] = 0xFFFFFFFFu; cmin[tid] = 0xFFFFFFFFu; }

    float acc[2][8][4];
#pragma unroll
    for (int mt = 0; mt < 2; mt++)
#pragma unroll
        for (int nt = 0; nt < 8; nt++)
#pragma unroll
            for (int e = 0; e < 4; e++) acc[mt][nt][e] = 0.f;

    stage_chunk(bi, bj, 0, Abuf[0], Bbuf[0], tid);
    asm volatile("cp.async.commit_group;");

#pragma unroll
    for (int kc = 0; kc < 2; kc++) {
        if (kc < 1) {
            stage_chunk(bi, bj, 1, Abuf[1], Bbuf[1], tid);
            asm volatile("cp.async.commit_group;");
            asm volatile("cp.async.wait_group 1;");
        } else {
            asm volatile("cp.async.wait_group 0;");
        }
        __syncthreads();

        const uint32_t* As = Abuf[kc];
        const uint32_t* Bs = Bbuf[kc];
#pragma unroll
        for (int ks = 0; ks < 4; ks++) {
            const int k0 = ks * 8;       // 8 words = 16 bf16 elements
            uint32_t a[2][4];
#pragma unroll
            for (int mt = 0; mt < 2; mt++) {
                int rbase = (wm * 32 + mt * 16 + g) * SPITCH + k0 + tig;
                a[mt][0] = As[rbase];
                a[mt][1] = As[rbase + 8 * SPITCH];
                a[mt][2] = As[rbase + 4];
                a[mt][3] = As[rbase + 8 * SPITCH + 4];
            }
            uint32_t b[8][2];
#pragma unroll
            for (int nt = 0; nt < 8; nt++) {
                int cbase = (wn * 64 + nt * 8 + g) * SPITCH + k0 + tig;
                b[nt][0] = Bs[cbase];
                b[nt][1] = Bs[cbase + 4];
            }
#pragma unroll
            for (int mt = 0; mt < 2; mt++)
#pragma unroll
                for (int nt = 0; nt < 8; nt++)
                    asm volatile(
                        "mma.sync.aligned.m16n8k16.row.col.f32.bf16.bf16.f32 "
                        "{%0,%1,%2,%3}, {%4,%5,%6,%7}, {%8,%9}, {%0,%1,%2,%3};"
                        : "+f"(acc[mt][nt][0]), "+f"(acc[mt][nt][1]),
                          "+f"(acc[mt][nt][2]), "+f"(acc[mt][nt][3])
                        : "r"(a[mt][0]), "r"(a[mt][1]), "r"(a[mt][2]), "r"(a[mt][3]),
                          "r"(b[nt][0]), "r"(b[nt][1]));
        }
        __syncthreads();
    }
    // staging smem is free from here on (reused as transpose buffer)

    const float INFV = __int_as_float(0x7f800000);
    float cm[8][2];
#pragma unroll
    for (int nt = 0; nt < 8; nt++) { cm[nt][0] = INFV; cm[nt][1] = INFV; }

#pragma unroll
    for (int mt = 0; mt < 2; mt++) {
        int rl = wm * 32 + mt * 16 + g;        // local row (lo); hi = +8
        int r_lo = bi + rl, r_hi = r_lo + 8;
        float si_lo = g_sq[r_lo], si_hi = g_sq[r_hi];
        float mn_lo = INFV, mn_hi = INFV;
#pragma unroll
        for (int nt = 0; nt < 8; nt++) {
            int cl = wn * 64 + nt * 8 + 2 * tig;   // local col
            int c0 = bj + cl;
            float sj0 = g_sq[c0], sj1 = g_sq[c0 + 1];
            float d00 = (si_lo + sj0) - 2.f * acc[mt][nt][0];
            float d01 = (si_lo + sj1) - 2.f * acc[mt][nt][1];
            float d10 = (si_hi + sj0) - 2.f * acc[mt][nt][2];
            float d11 = (si_hi + sj1) - 2.f * acc[mt][nt][3];
            if (r_lo == c0)     d00 = INFV;
            if (r_lo == c0 + 1) d01 = INFV;
            if (r_hi == c0)     d10 = INFV;
            if (r_hi == c0 + 1) d11 = INFV;
            __half h00 = __float2half_rn(d00), h01 = __float2half_rn(d01);
            __half h10 = __float2half_rn(d10), h11 = __float2half_rn(d11);
            float f00 = __half2float(h00), f01 = __half2float(h01);
            float f10 = __half2float(h10), f11 = __half2float(h11);
            mn_lo = fminf(mn_lo, fminf(f00, f01));
            mn_hi = fminf(mn_hi, fminf(f10, f11));
            *reinterpret_cast<__half2*>(&g_dist[(size_t)r_lo * N + c0]) =
                __halves2half2(h00, h01);
            *reinterpret_cast<__half2*>(&g_dist[(size_t)r_hi * N + c0]) =
                __halves2half2(h10, h11);
            if (mirror) {
                cm[nt][0] = fminf(cm[nt][0], fminf(f00, f10));
                cm[nt][1] = fminf(cm[nt][1], fminf(f01, f11));
                smf[cl * TPITCH + rl]           = f00;
                smf[(cl + 1) * TPITCH + rl]     = f01;
                smf[cl * TPITCH + rl + 8]       = f10;
                smf[(cl + 1) * TPITCH + rl + 8] = f11;
            }
        }
        mn_lo = fminf(mn_lo, __shfl_xor_sync(0xffffffffu, mn_lo, 1));
        mn_lo = fminf(mn_lo, __shfl_xor_sync(0xffffffffu, mn_lo, 2));
        mn_hi = fminf(mn_hi, __shfl_xor_sync(0xffffffffu, mn_hi, 1));
        mn_hi = fminf(mn_hi, __shfl_xor_sync(0xffffffffu, mn_hi, 2));
        if (tig == 0) {
            atomicMin(&rmin[wm * 32 + mt * 16 + g],     fkey(mn_lo));
            atomicMin(&rmin[wm * 32 + mt * 16 + g + 8], fkey(mn_hi));
        }
    }

    if (mirror) {
#pragma unroll
        for (int nt = 0; nt < 8; nt++)
#pragma unroll
            for (int e = 0; e < 2; e++) {
                float v = cm[nt][e];
                v = fminf(v, __shfl_xor_sync(0xffffffffu, v, 4));
                v = fminf(v, __shfl_xor_sync(0xffffffffu, v, 8));
                v = fminf(v, __shfl_xor_sync(0xffffffffu, v, 16));
                if (lane < 4)
                    atomicMin(&cmin[wn * 64 + nt * 8 + 2 * tig + e], fkey(v));
            }
    }
    __syncthreads();

    if (tid < 128)
        g_rowmin[(bi + tid) * NTILE + blockIdx.x] = funkey(rmin[tid]);

    if (mirror) {
        // coalesced mirrored-tile store (half round-trip is bit-exact)
#pragma unroll
        for (int it = 0; it < 16; it++) {
            int idx = tid + it * 256;     // 0..4095
            int tr  = idx >> 5;           // 0..127
            int c4  = (idx & 31) << 2;    // 0..124
            float4 v = *reinterpret_cast<const float4*>(&smf[tr * TPITCH + c4]);
            __half2 h0 = __halves2half2(__float2half_rn(v.x), __float2half_rn(v.y));
            __half2 h1 = __halves2half2(__float2half_rn(v.z), __float2half_rn(v.w));
            *reinterpret_cast<__half2*>(&g_dist[(size_t)(bj + tr) * N + bi + c4])     = h0;
            *reinterpret_cast<__half2*>(&g_dist[(size_t)(bj + tr) * N + bi + c4 + 2]) = h1;
        }
        if (tid < 128)
            g_rowmin[(bj + tid) * NTILE + blockIdx.y] = funkey(cmin[tid]);
    }
}

// ---------------------------------------------------------------------------
// 3) per-row top-20 via hierarchical tile-min selection.
//    tau = tile-min with rank KCAND-1 among the 128 tile minima (each is a
//    distinct element => >=KCAND elements <= tau, and tau is TIGHT).
//    Scan only tiles with min <= tau, compact, rank-select by (val, idx).
// ---------------------------------------------------------------------------
__global__ __launch_bounds__(128)
void topk_kernel() {
    __shared__ float tmin[NTILE];
    __shared__ float s_tau;
    __shared__ int   s_act[NTILE];
    __shared__ int   s_nact;
    __shared__ int   s_cnt;
    __shared__ float bval[BUFCAP];
    __shared__ int   bidx[BUFCAP];

    const int row  = blockIdx.x;
    const __half* d = g_dist + (size_t)row * N;
    const int tid  = threadIdx.x;

    tmin[tid] = g_rowmin[row * NTILE + tid];
    if (tid == 0) { s_cnt = 0; s_nact = 0; }
    __syncthreads();

    // tau = tile-min with rank KCAND-1 under (val, tile) order
    float mv = tmin[tid];
    int rank = 0;
#pragma unroll 8
    for (int t = 0; t < NTILE; t++) {
        float ov = tmin[t];
        rank += (ov < mv) || (ov == mv && t < tid);
    }
    if (rank == KCAND - 1) s_tau = mv;
    __syncthreads();
    const float tau = s_tau;

    // active tiles (min <= tau)
    if (tmin[tid] <= tau) {
        int p = atomicAdd(&s_nact, 1);
        s_act[p] = tid;
    }
    __syncthreads();
    const int nact = s_nact;

    // scan active tiles, compact elements <= tau
    for (int a = 0; a < nact; a++) {
        int t = s_act[a];
        float v = __half2float(d[t * 128 + tid]);
        if (v <= tau) {
            int p = atomicAdd(&s_cnt, 1);
            if (p < BUFCAP) { bval[p] = v; bidx[p] = t * 128 + tid; }
        }
    }
    __syncthreads();
    const int m = (s_cnt < BUFCAP) ? s_cnt : BUFCAP;

    // rank-select: entry e's rank = #{f : (v_f, i_f) < (v_e, i_e)}
    for (int e = tid; e < m; e += 128) {
        float v = bval[e];
        int   j = bidx[e];
        int r = 0;
        for (int t = 0; t < m; t++) {
            float ov = bval[t];
            r += (ov < v) || (ov == v && bidx[t] < j);
        }
        if (r < KCAND) g_cand[row * KCAND + r] = j;
    }
}

// ---------------------------------------------------------------------------
// 3b) authoritative fp32 re-rank of the 20 candidates (reference arithmetic).
//     One warp per row; lane t owns candidate t.
// ---------------------------------------------------------------------------
__global__ __launch_bounds__(128)
void refine_kernel(const float* __restrict__ x) {
    __shared__ float sxi[4][128];
    const int warp = threadIdx.x >> 5;
    const int lane = threadIdx.x & 31;
    const int row  = blockIdx.x * 4 + warp;

#pragma unroll
    for (int q = 0; q < 4; q++)
        sxi[warp][lane + 32 * q] = x[(size_t)row * C + lane + 32 * q];
    __syncwarp();

    float d = __int_as_float(0x7f800000);
    int   j = 0x7fffffff;
    if (lane < KCAND) {
        j = g_cand[row * KCAND + lane];
        const float* xj = x + (size_t)j * C;
        float acc = 0.f;
#pragma unroll
        for (int k = 0; k < C; k += 4) {
            float4 v = *reinterpret_cast<const float4*>(xj + k);
            acc = fmaf(sxi[warp][k + 0], v.x, acc);
            acc = fmaf(sxi[warp][k + 1], v.y, acc);
            acc = fmaf(sxi[warp][k + 2], v.z, acc);
            acc = fmaf(sxi[warp][k + 3], v.w, acc);
        }
        d = (g_sq[row] + g_sq[j]) - 2.f * acc;
    }

    float dv[KCAND];
    int   di[KCAND];
#pragma unroll
    for (int t = 0; t < KCAND; t++) {
        dv[t] = __shfl_sync(0xffffffffu, d, t);
        di[t] = __shfl_sync(0xffffffffu, j, t);
    }
    if (lane == 0) {
#pragma unroll
        for (int a = 0; a < KCAND - 1; a++)
#pragma unroll
            for (int bq = 0; bq < KCAND - 1; bq++) {
                bool sw = dv[bq] > dv[bq + 1] ||
                          (dv[bq] == dv[bq + 1] && di[bq] > di[bq + 1]);
                float tv = sw ? dv[bq + 1] : dv[bq];
                dv[bq + 1] = sw ? dv[bq] : dv[bq + 1]; dv[bq] = tv;
                int ti = sw ? di[bq + 1] : di[bq];
                di[bq + 1] = sw ? di[bq] : di[bq + 1]; di[bq] = ti;
            }
#pragma unroll
        for (int t = 0; t < KNN; t++) g_nbr[row * KNN + t] = di[t];
    }
}

// ---------------------------------------------------------------------------
// 4) x2 = x + rel_pos_table[rel]
// ---------------------------------------------------------------------------
__global__ void relpos_kernel(const float* __restrict__ x, const float* __restrict__ tab) {
    int idx = blockIdx.x * blockDim.x + threadIdx.x;
    int i   = idx >> 7;
    int c   = idx & 127;
    int rel = (i >> 7) - (i & 127) + (C - 1);
    g_x2[idx] = x[idx] + tab[(size_t)rel * C + c];
}

// ---------------------------------------------------------------------------
// 5) gather + max-relative + concat-GEMM (+ bias at the end). 16 rows/block.
// ---------------------------------------------------------------------------
__global__ __launch_bounds__(256)
void final_kernel(const float* __restrict__ W, const float* __restrict__ b,
                  float* __restrict__ out) {
    __shared__ float feat[16][260];
    const int r0   = blockIdx.x * 16;
    const int tid  = threadIdx.x;
    const int half = tid >> 7;
    const int c    = tid & 127;
    const float NEGINF = __int_as_float(0xff800000);

#pragma unroll
    for (int rr = 0; rr < 16; rr += 2) {
        int r = rr + half;
        int i = r0 + r;
        float xi = g_x2[(size_t)i * C + c];
        float m  = NEGINF;
#pragma unroll
        for (int k = 0; k < KNN; k++) {
            int j = g_nbr[i * KNN + k];
            m = fmaxf(m, g_x2[(size_t)j * C + c] - xi);
        }
        feat[r][c]     = xi;
        feat[r][C + c] = m;
    }
    __syncthreads();

    const int o = tid;
    float acc[16];
#pragma unroll
    for (int r = 0; r < 16; r++) acc[r] = 0.f;

    for (int f = 0; f < 2 * C; f += 4) {
        float w0 = W[(size_t)(f + 0) * COUT + o];
        float w1 = W[(size_t)(f + 1) * COUT + o];
        float w2 = W[(size_t)(f + 2) * COUT + o];
        float w3 = W[(size_t)(f + 3) * COUT + o];
#pragma unroll
        for (int r = 0; r < 16; r++) {
            float4 fv = *reinterpret_cast<const float4*>(&feat[r][f]);
            acc[r] = fmaf(fv.x, w0, acc[r]);
            acc[r] = fmaf(fv.y, w1, acc[r]);
            acc[r] = fmaf(fv.z, w2, acc[r]);
            acc[r] = fmaf(fv.w, w3, acc[r]);
        }
    }
    float bias = b[o];
#pragma unroll
    for (int r = 0; r < 16; r++)
        out[(size_t)(r0 + r) * COUT + o] = acc[r] + bias;
}

// ---------------------------------------------------------------------------
extern "C" void kernel_launch(void* const* d_in, const int* in_sizes, int n_in,
                              void* d_out, int out_size) {
    const float* x   = (const float*)d_in[0];
    const float* tab = (const float*)d_in[1];
    const float* W   = (const float*)d_in[2];
    const float* b   = (const float*)d_in[3];
    float* out = (float*)d_out;
    (void)in_sizes; (void)n_in; (void)out_size;

    const int smem_bytes = (4 * CHWORDS) * (int)sizeof(uint32_t) + 256 * (int)sizeof(unsigned);
    static bool attr_set = false;
    if (!attr_set) {
        cudaFuncSetAttribute(dist_kernel,
                             cudaFuncAttributeMaxDynamicSharedMemorySize, smem_bytes);
        attr_set = true;
    }

    prep_kernel<<<(N + 255) / 256, 256>>>(x);
    dist_kernel<<<dim3(NTILE, NTILE), 256, smem_bytes>>>();
    topk_kernel<<<N, 128>>>();
    refine_kernel<<<N / 4, 128>>>(x);
    relpos_kernel<<<(N * C) / 256, 256>>>(x, tab);
    final_kernel<<<N / 16, 256>>>(W, b, out);
}